// round 5
// baseline (speedup 1.0000x reference)
#include <cuda_runtime.h>
#include <math.h>
#include <stdint.h>

// ---------------- constants ----------------
#define NCHUNK 32
#define EVCAP  204800

// ---------------- device scratch (single symbol, offsets) ----------------
static constexpr size_t O_KV = 0;                                   // (EVCAP,512) k|v
static constexpr size_t O_NW = O_KV + (size_t)EVCAP * 512;          // 4096x512
static constexpr size_t O_TW = O_NW + (size_t)4096 * 512;           // 1024x512
static constexpr size_t O_VW = O_TW + (size_t)1024 * 512;           // 256x512
static constexpr size_t O_CS = O_VW + (size_t)256 * 512;            // 512 colsum
static constexpr size_t O_CSP = O_CS + 512;                         // 16x512 colsum partials
static constexpr size_t O_Q  = O_CSP + 16 * 512;                    // (H,64,32)
static constexpr size_t O_PO = O_Q + 8 * 64 * 32;                   // (B,H,NCHUNK,64,32)
static constexpr size_t O_PZ = O_PO + (size_t)16 * 8 * NCHUNK * 64 * 32; // (B,H,NCHUNK,64)
static constexpr size_t O_LAT = O_PZ + (size_t)16 * 8 * NCHUNK * 64;
static constexpr size_t O_LN  = O_LAT + 1024 * 256;
static constexpr size_t O_T1  = O_LN + 1024 * 256;                  // 1024x1024
static constexpr size_t O_T2  = O_T1 + 1024 * 1024;                 // 1024x768
static constexpr size_t O_AT  = O_T2 + 1024 * 768;
static constexpr size_t O_XB  = O_AT + 1024 * 256;
static constexpr size_t O_KB  = O_XB + 1024 * 256;                  // 1024x512
static constexpr size_t O_QB  = O_KB + 1024 * 512;                  // (H,2,32)
static constexpr size_t O_BO  = O_QB + 512;                         // (B,2,256)
static constexpr size_t O_MEAN = O_BO + 16 * 2 * 256;               // (B,256)
static constexpr size_t SCRATCH_TOTAL = O_MEAN + 16 * 256;

__device__ float g_buf[SCRATCH_TOTAL];

__device__ __forceinline__ float gelu_f(float x) {
    float x3 = x * x * x;
    return 0.5f * x * (1.0f + tanhf(0.7978845608028654f * (x + 0.044715f * x3)));
}

// ---------------- tiled GEMM 128x64 + epilogue ----------------
// C(MxN) = A(MxK) @ W(KxN); optional bias[c], gelu, residual res[(r%resMod)*N + c]
// Requires M%128==0, N%64==0, K%16==0.
__global__ __launch_bounds__(256) void gemm_epi(
    const float* __restrict__ A, const float* __restrict__ W, float* __restrict__ C,
    int M, int K, int N, const float* __restrict__ res, int resMod,
    const float* __restrict__ bias, int doGelu)
{
    __shared__ float As[16][136];
    __shared__ float Bs[16][64];
    int t = threadIdx.x;
    int tx = t & 15, ty = t >> 4;           // tx: 4-col group, ty: 8-row group
    int row0 = blockIdx.y * 128, col0 = blockIdx.x * 64;
    float acc[8][4] = {};
    int br = t >> 4, bc = (t & 15) * 4;
    for (int k0 = 0; k0 < K; k0 += 16) {
#pragma unroll
        for (int i = 0; i < 2; i++) {
            int s = t + i * 256;            // 512 float4 slots for A tile
            int r = s >> 2, c4 = (s & 3) * 4;
            float4 a4 = *(const float4*)(A + (size_t)(row0 + r) * K + k0 + c4);
            As[c4 + 0][r] = a4.x; As[c4 + 1][r] = a4.y;
            As[c4 + 2][r] = a4.z; As[c4 + 3][r] = a4.w;
        }
        *(float4*)&Bs[br][bc] = *(const float4*)(W + (size_t)(k0 + br) * N + col0 + bc);
        __syncthreads();
#pragma unroll
        for (int kk = 0; kk < 16; kk++) {
            float4 a0 = *(const float4*)&As[kk][ty * 8];
            float4 a1 = *(const float4*)&As[kk][ty * 8 + 4];
            float4 bv = *(const float4*)&Bs[kk][tx * 4];
            acc[0][0] += a0.x * bv.x; acc[0][1] += a0.x * bv.y; acc[0][2] += a0.x * bv.z; acc[0][3] += a0.x * bv.w;
            acc[1][0] += a0.y * bv.x; acc[1][1] += a0.y * bv.y; acc[1][2] += a0.y * bv.z; acc[1][3] += a0.y * bv.w;
            acc[2][0] += a0.z * bv.x; acc[2][1] += a0.z * bv.y; acc[2][2] += a0.z * bv.z; acc[2][3] += a0.z * bv.w;
            acc[3][0] += a0.w * bv.x; acc[3][1] += a0.w * bv.y; acc[3][2] += a0.w * bv.z; acc[3][3] += a0.w * bv.w;
            acc[4][0] += a1.x * bv.x; acc[4][1] += a1.x * bv.y; acc[4][2] += a1.x * bv.z; acc[4][3] += a1.x * bv.w;
            acc[5][0] += a1.y * bv.x; acc[5][1] += a1.y * bv.y; acc[5][2] += a1.y * bv.z; acc[5][3] += a1.y * bv.w;
            acc[6][0] += a1.z * bv.x; acc[6][1] += a1.z * bv.y; acc[6][2] += a1.z * bv.z; acc[6][3] += a1.z * bv.w;
            acc[7][0] += a1.w * bv.x; acc[7][1] += a1.w * bv.y; acc[7][2] += a1.w * bv.z; acc[7][3] += a1.w * bv.w;
        }
        __syncthreads();
    }
#pragma unroll
    for (int i = 0; i < 8; i++) {
        int r = row0 + ty * 8 + i;
#pragma unroll
        for (int j = 0; j < 4; j++) {
            int c = col0 + tx * 4 + j;
            float v = acc[i][j];
            if (bias) v += bias[c];
            if (doGelu) v = gelu_f(v);
            if (res) v += res[(size_t)(r % resMod) * N + c];
            C[(size_t)r * N + c] = v;
        }
    }
}

// ---------------- colsum of Wkv (512): deterministic 2-pass ----------------
__global__ void colsum_part(const float* __restrict__ Wkv, float* __restrict__ part) {
    int c = threadIdx.x;                 // 512
    int r0 = blockIdx.x * 16;            // 16 blocks
    float s = 0.f;
#pragma unroll
    for (int k = 0; k < 16; k++) s += Wkv[(r0 + k) * 512 + c];
    part[blockIdx.x * 512 + c] = s;
}
__global__ void colsum_reduce(const float* __restrict__ part, float* __restrict__ cs) {
    int c = threadIdx.x;                 // 512
    float s = 0.f;
#pragma unroll
    for (int i = 0; i < 16; i++) s += part[i * 512 + c];
    cs[c] = s;
}

// ---------------- per-event KV: LN stats from raw rows, combine projected rows ----------------
__global__ __launch_bounds__(256) void event_kv_kernel(
    const int* __restrict__ nid, const int* __restrict__ tbi, const int* __restrict__ vli,
    const float* __restrict__ nemb, const float* __restrict__ temb, const float* __restrict__ vemb,
    const float* __restrict__ nW, const float* __restrict__ tW, const float* __restrict__ vW,
    const float* __restrict__ colsum, float* __restrict__ KV, int E)
{
    __shared__ float sMean[32], sInv[32];
    __shared__ int sNi[32], sTi[32], sVi[32];
    int t = threadIdx.x;
    int le = t >> 3, g8 = t & 7;
    int base = blockIdx.x * 32;
    int e = base + le;
    float s = 0.f, sq = 0.f;
    if (e < E) {
        int ni = nid[e], ti = tbi[e], vi = vli[e];
        if (g8 == 0) { sNi[le] = ni; sTi[le] = ti; sVi[le] = vi; }
        const float* np = nemb + (size_t)ni * 256;
        const float* tp = temb + (size_t)ti * 256;
        const float* vp = vemb + (size_t)vi * 256;
#pragma unroll
        for (int i = 0; i < 8; i++) {
            int d = g8 * 32 + i * 4;
            float4 a = *(const float4*)(np + d);
            float4 b = *(const float4*)(tp + d);
            float4 c = *(const float4*)(vp + d);
            float x0 = a.x + b.x + c.x, x1 = a.y + b.y + c.y;
            float x2 = a.z + b.z + c.z, x3 = a.w + b.w + c.w;
            s += x0 + x1 + x2 + x3;
            sq += x0 * x0 + x1 * x1 + x2 * x2 + x3 * x3;
        }
    }
    s += __shfl_xor_sync(0xffffffffu, s, 1);
    s += __shfl_xor_sync(0xffffffffu, s, 2);
    s += __shfl_xor_sync(0xffffffffu, s, 4);
    sq += __shfl_xor_sync(0xffffffffu, sq, 1);
    sq += __shfl_xor_sync(0xffffffffu, sq, 2);
    sq += __shfl_xor_sync(0xffffffffu, sq, 4);
    if (g8 == 0 && e < E) {
        float mean = s * (1.0f / 256.0f);
        float var = sq * (1.0f / 256.0f) - mean * mean;
        sMean[le] = mean;
        sInv[le] = rsqrtf(var + 1e-5f);
    }
    __syncthreads();
    int nE = E - base; if (nE > 32) nE = 32;
    float cs0 = colsum[t], cs1 = colsum[t + 256];
#pragma unroll 4
    for (int ee = 0; ee < nE; ee++) {
        int ni = sNi[ee], ti = sTi[ee], vi = sVi[ee];
        float inv = sInv[ee];
        float mi = sMean[ee] * inv;
        float p0 = nW[(size_t)ni * 512 + t] + tW[(size_t)ti * 512 + t] + vW[(size_t)vi * 512 + t];
        float p1 = nW[(size_t)ni * 512 + 256 + t] + tW[(size_t)ti * 512 + 256 + t] + vW[(size_t)vi * 512 + 256 + t];
        KV[(size_t)(base + ee) * 512 + t] = inv * p0 - mi * cs0;
        KV[(size_t)(base + ee) * 512 + 256 + t] = inv * p1 - mi * cs1;
    }
}

// ---------------- generic LayerNorm: one warp per row, 256-dim ----------------
__global__ void ln_kernel(const float* __restrict__ X, float* __restrict__ Y,
                          const float* __restrict__ w, const float* __restrict__ b, int rows)
{
    int row = blockIdx.x * 8 + (threadIdx.x >> 5);
    int lane = threadIdx.x & 31;
    if (row >= rows) return;
    const float* x = X + (size_t)row * 256;
    float v[8]; float s = 0.f, sq = 0.f;
#pragma unroll
    for (int i = 0; i < 8; i++) { v[i] = x[lane + 32 * i]; s += v[i]; sq += v[i] * v[i]; }
#pragma unroll
    for (int o = 16; o > 0; o >>= 1) {
        s += __shfl_xor_sync(0xffffffffu, s, o);
        sq += __shfl_xor_sync(0xffffffffu, sq, o);
    }
    float mean = s * (1.0f / 256.0f);
    float var = sq * (1.0f / 256.0f) - mean * mean;
    float inv = rsqrtf(var + 1e-5f);
    float* y = Y + (size_t)row * 256;
#pragma unroll
    for (int i = 0; i < 8; i++) {
        int d = lane + 32 * i;
        float o = (v[i] - mean) * inv;
        if (w) o = o * w[d] + b[d];
        y[d] = o;
    }
}

// ---------------- cross-attn Q: ln(lat_init) @ Wq -> heads, pre-scaled ----------------
__global__ void qc_kernel(const float* __restrict__ lnlat, const float* __restrict__ Wq,
                          float* __restrict__ qout)
{
    int l = blockIdx.x;        // 64
    int c = threadIdx.x;       // 256
    float s = 0.f;
    for (int k = 0; k < 256; k++) s += lnlat[l * 256 + k] * Wq[k * 256 + c];
    int h = c >> 5, dh = c & 31;
    qout[(h * 64 + l) * 32 + dh] = s * 0.17677669529663689f;  // 1/sqrt(32)
}

// ---------------- cross-attn scan over ragged events (deterministic, MLP-unrolled) ----------------
__global__ __launch_bounds__(256) void attn_scan_kernel(
    const int* __restrict__ bidx, const float* __restrict__ KV, const float* __restrict__ qg,
    float* __restrict__ pO, float* __restrict__ pZ, int E)
{
    int chunk = blockIdx.x, b = blockIdx.y, h = blockIdx.z;
    int per = (E + NCHUNK - 1) / NCHUNK;
    int s0 = chunk * per;
    int s1 = s0 + per; if (s1 > E) s1 = E;
    __shared__ float sq[2048];
    __shared__ int list[256];
    __shared__ int wcnt[8];
    int t = threadIdx.x;
    for (int i = t; i < 2048; i += 256) sq[i] = qg[h * 2048 + i];
    __syncthreads();
    int l = t >> 2, r = t & 3;
    float qv[8];
#pragma unroll
    for (int j = 0; j < 8; j++) qv[j] = sq[l * 32 + r * 8 + j];
    float accO[8] = {0.f, 0.f, 0.f, 0.f, 0.f, 0.f, 0.f, 0.f};
    float accZ = 0.f;
    int w = t >> 5, lane = t & 31;
    int hoff = h * 32 + r * 8;
    for (int base = s0; base < s1; base += 256) {
        int e = base + t;
        bool m = (e < s1) && (bidx[e] == b);
        unsigned bm = __ballot_sync(0xffffffffu, m);
        if (lane == 0) wcnt[w] = __popc(bm);
        __syncthreads();
        int ofs = 0, total = 0;
#pragma unroll
        for (int ww = 0; ww < 8; ww++) { int c = wcnt[ww]; if (ww < w) ofs += c; total += c; }
        if (m) list[ofs + __popc(bm & ((1u << lane) - 1u))] = e;
        __syncthreads();
        int nb4 = total & ~3;
        for (int i = 0; i < nb4; i += 4) {
            const float* p0 = KV + (size_t)list[i + 0] * 512 + hoff;
            const float* p1 = KV + (size_t)list[i + 1] * 512 + hoff;
            const float* p2 = KV + (size_t)list[i + 2] * 512 + hoff;
            const float* p3 = KV + (size_t)list[i + 3] * 512 + hoff;
            float4 ka0 = *(const float4*)p0, kb0 = *(const float4*)(p0 + 4);
            float4 ka1 = *(const float4*)p1, kb1 = *(const float4*)(p1 + 4);
            float4 ka2 = *(const float4*)p2, kb2 = *(const float4*)(p2 + 4);
            float4 ka3 = *(const float4*)p3, kb3 = *(const float4*)(p3 + 4);
            float4 va0 = *(const float4*)(p0 + 256), vb0 = *(const float4*)(p0 + 260);
            float4 va1 = *(const float4*)(p1 + 256), vb1 = *(const float4*)(p1 + 260);
            float4 va2 = *(const float4*)(p2 + 256), vb2 = *(const float4*)(p2 + 260);
            float4 va3 = *(const float4*)(p3 + 256), vb3 = *(const float4*)(p3 + 260);
            float t0 = qv[0]*ka0.x + qv[1]*ka0.y + qv[2]*ka0.z + qv[3]*ka0.w
                     + qv[4]*kb0.x + qv[5]*kb0.y + qv[6]*kb0.z + qv[7]*kb0.w;
            float t1 = qv[0]*ka1.x + qv[1]*ka1.y + qv[2]*ka1.z + qv[3]*ka1.w
                     + qv[4]*kb1.x + qv[5]*kb1.y + qv[6]*kb1.z + qv[7]*kb1.w;
            float t2 = qv[0]*ka2.x + qv[1]*ka2.y + qv[2]*ka2.z + qv[3]*ka2.w
                     + qv[4]*kb2.x + qv[5]*kb2.y + qv[6]*kb2.z + qv[7]*kb2.w;
            float t3 = qv[0]*ka3.x + qv[1]*ka3.y + qv[2]*ka3.z + qv[3]*ka3.w
                     + qv[4]*kb3.x + qv[5]*kb3.y + qv[6]*kb3.z + qv[7]*kb3.w;
            t0 += __shfl_xor_sync(0xffffffffu, t0, 1);
            t1 += __shfl_xor_sync(0xffffffffu, t1, 1);
            t2 += __shfl_xor_sync(0xffffffffu, t2, 1);
            t3 += __shfl_xor_sync(0xffffffffu, t3, 1);
            t0 += __shfl_xor_sync(0xffffffffu, t0, 2);
            t1 += __shfl_xor_sync(0xffffffffu, t1, 2);
            t2 += __shfl_xor_sync(0xffffffffu, t2, 2);
            t3 += __shfl_xor_sync(0xffffffffu, t3, 2);
            float e0 = __expf(t0), e1 = __expf(t1), e2 = __expf(t2), e3 = __expf(t3);
            if (r == 0) { accZ += e0; accZ += e1; accZ += e2; accZ += e3; }
            accO[0] += e0*va0.x; accO[0] += e1*va1.x; accO[0] += e2*va2.x; accO[0] += e3*va3.x;
            accO[1] += e0*va0.y; accO[1] += e1*va1.y; accO[1] += e2*va2.y; accO[1] += e3*va3.y;
            accO[2] += e0*va0.z; accO[2] += e1*va1.z; accO[2] += e2*va2.z; accO[2] += e3*va3.z;
            accO[3] += e0*va0.w; accO[3] += e1*va1.w; accO[3] += e2*va2.w; accO[3] += e3*va3.w;
            accO[4] += e0*vb0.x; accO[4] += e1*vb1.x; accO[4] += e2*vb2.x; accO[4] += e3*vb3.x;
            accO[5] += e0*vb0.y; accO[5] += e1*vb1.y; accO[5] += e2*vb2.y; accO[5] += e3*vb3.y;
            accO[6] += e0*vb0.z; accO[6] += e1*vb1.z; accO[6] += e2*vb2.z; accO[6] += e3*vb3.z;
            accO[7] += e0*vb0.w; accO[7] += e1*vb1.w; accO[7] += e2*vb2.w; accO[7] += e3*vb3.w;
        }
        for (int i = nb4; i < total; i++) {
            const float* kp = KV + (size_t)list[i] * 512 + hoff;
            float4 k0 = *(const float4*)kp;
            float4 k1 = *(const float4*)(kp + 4);
            float part = qv[0]*k0.x + qv[1]*k0.y + qv[2]*k0.z + qv[3]*k0.w
                       + qv[4]*k1.x + qv[5]*k1.y + qv[6]*k1.z + qv[7]*k1.w;
            part += __shfl_xor_sync(0xffffffffu, part, 1);
            part += __shfl_xor_sync(0xffffffffu, part, 2);
            float p = __expf(part);
            if (r == 0) accZ += p;
            float4 v0 = *(const float4*)(kp + 256);
            float4 v1 = *(const float4*)(kp + 260);
            accO[0] += p * v0.x; accO[1] += p * v0.y; accO[2] += p * v0.z; accO[3] += p * v0.w;
            accO[4] += p * v1.x; accO[5] += p * v1.y; accO[6] += p * v1.z; accO[7] += p * v1.w;
        }
        __syncthreads();
    }
    size_t pb = (size_t)((b * 8 + h) * NCHUNK + chunk);
#pragma unroll
    for (int j = 0; j < 8; j++) pO[pb * 2048 + l * 32 + r * 8 + j] = accO[j];
    if (r == 0) pZ[pb * 64 + l] = accZ;
}

// ---------------- combine chunk partials -> attn output (B*L, 256) ----------------
__global__ void attn_combine_kernel(const float* __restrict__ pO, const float* __restrict__ pZ,
                                    float* __restrict__ attn)
{
    int bh = blockIdx.x;        // 0..127
    int b = bh >> 3, h = bh & 7;
    int t = threadIdx.x;
    __shared__ float sz[64];
    if (t < 64) {
        float z = 0.f;
        for (int c = 0; c < NCHUNK; c++) z += pZ[((size_t)bh * NCHUNK + c) * 64 + t];
        sz[t] = 1.0f / z;
    }
    __syncthreads();
    for (int i = t; i < 2048; i += 256) {
        int l = i >> 5, d = i & 31;
        float s = 0.f;
        for (int c = 0; c < NCHUNK; c++) s += pO[((size_t)bh * NCHUNK + c) * 2048 + i];
        attn[(size_t)(b * 64 + l) * 256 + h * 32 + d] = s * sz[l];
    }
}

// ---------------- small self-attention over latents, per (b,h) ----------------
__global__ __launch_bounds__(256) void self_attn_kernel(const float* __restrict__ qkv,
                                                        float* __restrict__ out)
{
    int b = blockIdx.x, h = blockIdx.y;
    __shared__ float sk[2048], sv[2048];
    int t = threadIdx.x;
    for (int i = t; i < 2048; i += 256) {
        int key = i >> 5, d = i & 31;
        size_t rowb = (size_t)(b * 64 + key) * 768;
        sk[i] = qkv[rowb + 256 + h * 32 + d];
        sv[i] = qkv[rowb + 512 + h * 32 + d];
    }
    __syncthreads();
    int ql = t >> 2, r = t & 3;
    const float* qp = qkv + (size_t)(b * 64 + ql) * 768 + h * 32 + r * 8;
    float qv[8];
#pragma unroll
    for (int j = 0; j < 8; j++) qv[j] = qp[j] * 0.17677669529663689f;
    float z = 0.f;
    for (int key = 0; key < 64; key++) {
        float part = 0.f;
#pragma unroll
        for (int j = 0; j < 8; j++) part += qv[j] * sk[key * 32 + r * 8 + j];
        part += __shfl_xor_sync(0xffffffffu, part, 1);
        part += __shfl_xor_sync(0xffffffffu, part, 2);
        z += __expf(part);
    }
    float o[8] = {0.f, 0.f, 0.f, 0.f, 0.f, 0.f, 0.f, 0.f};
    for (int key = 0; key < 64; key++) {
        float part = 0.f;
#pragma unroll
        for (int j = 0; j < 8; j++) part += qv[j] * sk[key * 32 + r * 8 + j];
        part += __shfl_xor_sync(0xffffffffu, part, 1);
        part += __shfl_xor_sync(0xffffffffu, part, 2);
        float p = __expf(part);
#pragma unroll
        for (int j = 0; j < 8; j++) o[j] += p * sv[key * 32 + r * 8 + j];
    }
    float invz = 1.0f / z;
#pragma unroll
    for (int j = 0; j < 8; j++)
        out[(size_t)(b * 64 + ql) * 256 + h * 32 + r * 8 + j] = o[j] * invz;
}

// ---------------- behavior query: (bh_query @ bh_wq) -> heads, pre-scaled ----------------
__global__ void qb_kernel(const float* __restrict__ bhq, const float* __restrict__ wq,
                          float* __restrict__ qb)
{
    int t = threadIdx.x;  // 512
    int be = t >> 8, c = t & 255;
    float s = 0.f;
    for (int k = 0; k < 256; k++) s += bhq[be * 256 + k] * wq[k * 256 + c];
    int h = c >> 5, dh = c & 31;
    qb[(h * 2 + be) * 32 + dh] = s * 0.17677669529663689f;
}

// ---------------- behavior attention per (b,h): 2 queries x 64 keys ----------------
__global__ void bh_attn_kernel(const float* __restrict__ kvb, const float* __restrict__ qb,
                               float* __restrict__ bo)
{
    int b = blockIdx.x, h = blockIdx.y;
    __shared__ float sk[2048], sv[2048];
    int t = threadIdx.x;  // 64
    for (int i = t; i < 2048; i += 64) {
        int key = i >> 5, d = i & 31;
        size_t rowb = (size_t)(b * 64 + key) * 512;
        sk[i] = kvb[rowb + h * 32 + d];
        sv[i] = kvb[rowb + 256 + h * 32 + d];
    }
    __syncthreads();
    int be = t >> 5, d = t & 31;
    float q[32];
#pragma unroll
    for (int j = 0; j < 32; j++) q[j] = qb[(h * 2 + be) * 32 + j];
    float z = 0.f, o = 0.f;
    for (int key = 0; key < 64; key++) {
        float s = 0.f;
#pragma unroll
        for (int j = 0; j < 32; j++) s += q[j] * sk[key * 32 + j];
        float p = __expf(s);
        z += p;
        o += p * sv[key * 32 + d];
    }
    bo[(size_t)(b * 2 + be) * 256 + h * 32 + d] = o / z;
}

// ---------------- behavior output: bo(32x256) @ wo(256) -> d_out[0..32) ----------------
__global__ void bh_out_kernel(const float* __restrict__ bo, const float* __restrict__ wo,
                              float* __restrict__ outBeh)
{
    int t = threadIdx.x;  // 1024
    int row = t >> 5, lane = t & 31;
    float s = 0.f;
#pragma unroll
    for (int i = 0; i < 8; i++) s += bo[row * 256 + lane + 32 * i] * wo[lane + 32 * i];
#pragma unroll
    for (int o = 16; o > 0; o >>= 1) s += __shfl_xor_sync(0xffffffffu, s, o);
    if (lane == 0) outBeh[row] = s;
}

// ---------------- mean over latents ----------------
__global__ void mean_kernel(const float* __restrict__ lat, float* __restrict__ mn)
{
    int b = blockIdx.x, d = threadIdx.x;  // 256
    float s = 0.f;
    for (int l = 0; l < 64; l++) s += lat[(size_t)(b * 64 + l) * 256 + d];
    mn[b * 256 + d] = s * (1.0f / 64.0f);
}

// ---------------- logits: mean(16x256) @ sp_w(256x64) + sp_b ----------------
__global__ void logits_kernel(const float* __restrict__ mn, const float* __restrict__ spw,
                              const float* __restrict__ spb, float* __restrict__ out)
{
    int t = threadIdx.x;  // 1024
    int b = t >> 6, s = t & 63;
    float acc = spb[s];
    for (int k = 0; k < 256; k++) acc += mn[b * 256 + k] * spw[k * 64 + s];
    out[b * 64 + s] = acc;
}

// ---------------- host launcher ----------------
extern "C" void kernel_launch(void* const* d_in, const int* in_sizes, int n_in,
                              void* d_out, int out_size)
{
    int ib, wb;
    if (in_sizes[0] == in_sizes[1] && in_sizes[1] == in_sizes[2] && in_sizes[2] == in_sizes[3]) {
        ib = 0; wb = n_in - 21;
    } else {
        wb = 0; ib = 21;
    }
    const int* nid  = (const int*)d_in[ib + 0];
    const int* tbi  = (const int*)d_in[ib + 1];
    const int* vli  = (const int*)d_in[ib + 2];
    const int* bidx = (const int*)d_in[ib + 3];
    int E = in_sizes[ib];
    if (E > EVCAP) E = EVCAP;

    const float* nemb    = (const float*)d_in[wb + 0];
    const float* temb    = (const float*)d_in[wb + 1];
    const float* vemb    = (const float*)d_in[wb + 2];
    const float* lat0    = (const float*)d_in[wb + 3];
    const float* Wq_c    = (const float*)d_in[wb + 4];
    const float* Wkv_c   = (const float*)d_in[wb + 5];
    const float* Wo_c    = (const float*)d_in[wb + 6];
    const float* W1_c    = (const float*)d_in[wb + 7];
    const float* W2_c    = (const float*)d_in[wb + 8];
    const float* Wqkv_s  = (const float*)d_in[wb + 9];
    const float* Wo_s    = (const float*)d_in[wb + 10];
    const float* W1_s    = (const float*)d_in[wb + 11];
    const float* W2_s    = (const float*)d_in[wb + 12];
    const float* bh_query = (const float*)d_in[wb + 13];
    const float* bh_wq   = (const float*)d_in[wb + 14];
    const float* bh_wkv  = (const float*)d_in[wb + 15];
    const float* bh_wo   = (const float*)d_in[wb + 16];
    const float* bh_ln_w = (const float*)d_in[wb + 17];
    const float* bh_ln_b = (const float*)d_in[wb + 18];
    const float* sp_w    = (const float*)d_in[wb + 19];
    const float* sp_b    = (const float*)d_in[wb + 20];

    float* buf = nullptr;
    cudaGetSymbolAddress((void**)&buf, g_buf);
    float* KV   = buf + O_KV;
    float* nW   = buf + O_NW;
    float* tW   = buf + O_TW;
    float* vW   = buf + O_VW;
    float* CS   = buf + O_CS;
    float* CSP  = buf + O_CSP;
    float* Qg   = buf + O_Q;
    float* PO   = buf + O_PO;
    float* PZ   = buf + O_PZ;
    float* LAT  = buf + O_LAT;
    float* LNB  = buf + O_LN;
    float* T1   = buf + O_T1;
    float* T2   = buf + O_T2;
    float* AT   = buf + O_AT;
    float* XB   = buf + O_XB;
    float* KB   = buf + O_KB;
    float* QB   = buf + O_QB;
    float* BO   = buf + O_BO;
    float* MN   = buf + O_MEAN;
    float* out = (float*)d_out;

    // --- Phase A: KV projection via precomputed embedding projections ---
    gemm_epi<<<dim3(8, 32), 256>>>(nemb, Wkv_c, nW, 4096, 256, 512, nullptr, 1, nullptr, 0);
    gemm_epi<<<dim3(8, 8), 256>>>(temb, Wkv_c, tW, 1024, 256, 512, nullptr, 1, nullptr, 0);
    gemm_epi<<<dim3(8, 2), 256>>>(vemb, Wkv_c, vW, 256, 256, 512, nullptr, 1, nullptr, 0);
    colsum_part<<<16, 512>>>(Wkv_c, CSP);
    colsum_reduce<<<1, 512>>>(CSP, CS);
    int EB = (E + 31) / 32;
    event_kv_kernel<<<EB, 256>>>(nid, tbi, vli, nemb, temb, vemb, nW, tW, vW, CS, KV, E);

    // --- Cross-attention ---
    ln_kernel<<<8, 256>>>(lat0, LNB, nullptr, nullptr, 64);
    qc_kernel<<<64, 256>>>(LNB, Wq_c, Qg);
    attn_scan_kernel<<<dim3(NCHUNK, 16, 8), 256>>>(bidx, KV, Qg, PO, PZ, E);
    attn_combine_kernel<<<128, 256>>>(PO, PZ, AT);

    // lat = lat_init + attn @ Wo_c
    gemm_epi<<<dim3(4, 8), 256>>>(AT, Wo_c, LAT, 1024, 256, 256, lat0, 64, nullptr, 0);
    // lat += gelu(ln(lat) @ W1_c) @ W2_c
    ln_kernel<<<128, 256>>>(LAT, LNB, nullptr, nullptr, 1024);
    gemm_epi<<<dim3(16, 8), 256>>>(LNB, W1_c, T1, 1024, 256, 1024, nullptr, 1, nullptr, 1);
    gemm_epi<<<dim3(4, 8), 256>>>(T1, W2_c, LAT, 1024, 1024, 256, LAT, 1024, nullptr, 0);

    // --- Self-attention layers ---
    for (int i = 0; i < 2; i++) {
        ln_kernel<<<128, 256>>>(LAT, LNB, nullptr, nullptr, 1024);
        gemm_epi<<<dim3(12, 8), 256>>>(LNB, Wqkv_s + (size_t)i * 256 * 768, T2, 1024, 256, 768,
                                       nullptr, 1, nullptr, 0);
        self_attn_kernel<<<dim3(16, 8), 256>>>(T2, AT);
        gemm_epi<<<dim3(4, 8), 256>>>(AT, Wo_s + (size_t)i * 256 * 256, LAT, 1024, 256, 256,
                                      LAT, 1024, nullptr, 0);
        ln_kernel<<<128, 256>>>(LAT, LNB, nullptr, nullptr, 1024);
        gemm_epi<<<dim3(16, 8), 256>>>(LNB, W1_s + (size_t)i * 256 * 1024, T1, 1024, 256, 1024,
                                       nullptr, 1, nullptr, 1);
        gemm_epi<<<dim3(4, 8), 256>>>(T1, W2_s + (size_t)i * 1024 * 256, LAT, 1024, 1024, 256,
                                      LAT, 1024, nullptr, 0);
    }

    // --- Behavior decoder ---
    ln_kernel<<<128, 256>>>(LAT, XB, bh_ln_w, bh_ln_b, 1024);
    qb_kernel<<<1, 512>>>(bh_query, bh_wq, QB);
    gemm_epi<<<dim3(8, 8), 256>>>(XB, bh_wkv, KB, 1024, 256, 512, nullptr, 1, nullptr, 0);
    bh_attn_kernel<<<dim3(16, 8), 64>>>(KB, QB, BO);
    bh_out_kernel<<<1, 1024>>>(BO, bh_wo, out);

    // --- Spike head ---
    mean_kernel<<<16, 256>>>(LAT, MN);
    logits_kernel<<<1, 1024>>>(MN, sp_w, sp_b, out + 32);
}

// round 8
// speedup vs baseline: 1.4671x; 1.4671x over previous
#include <cuda_runtime.h>
#include <math.h>
#include <stdint.h>

// ---------------- constants ----------------
#define NCHUNK 32
#define EVCAP  204800

// ---------------- float scratch ----------------
static constexpr size_t O_KV = 0;                                   // (EVCAP,512) sorted k|v
static constexpr size_t O_NW = O_KV + (size_t)EVCAP * 512;          // 4096x512
static constexpr size_t O_TW = O_NW + (size_t)4096 * 512;           // 1024x512
static constexpr size_t O_VW = O_TW + (size_t)1024 * 512;           // 256x512
static constexpr size_t O_CS = O_VW + (size_t)256 * 512;            // 512 colsum
static constexpr size_t O_Q  = O_CS + 512;                          // (H,64,32)
static constexpr size_t O_PO = O_Q + 8 * 64 * 32;                   // (B,H,NCHUNK,64,32)
static constexpr size_t O_PZ = O_PO + (size_t)16 * 8 * NCHUNK * 64 * 32;
static constexpr size_t O_LAT = O_PZ + (size_t)16 * 8 * NCHUNK * 64;
static constexpr size_t O_LN  = O_LAT + 1024 * 256;
static constexpr size_t O_T1  = O_LN + 1024 * 256;
static constexpr size_t O_T2  = O_T1 + 1024 * 1024;
static constexpr size_t O_AT  = O_T2 + 1024 * 768;
static constexpr size_t O_XB  = O_AT + 1024 * 256;
static constexpr size_t O_KB  = O_XB + 1024 * 256;
static constexpr size_t O_QB  = O_KB + 1024 * 512;
static constexpr size_t O_BO2 = O_QB + 512;
static constexpr size_t O_MEAN = O_BO2 + 16 * 2 * 256;
static constexpr size_t SCRATCH_TOTAL = O_MEAN + 16 * 256;

__device__ float g_buf[SCRATCH_TOTAL];

// ---------------- int scratch (sorting) ----------------
static constexpr size_t I_CNT  = 0;            // 6400*16 per-32-subgroup counts
static constexpr size_t I_BASE = 102400;       // 6400*16 within-batch prefix
static constexpr size_t I_BO   = 204800;       // 17 batch offsets
__device__ int g_ibuf[204832];

__device__ __forceinline__ float gelu_f(float x) {
    float x3 = x * x * x;
    return 0.5f * x * (1.0f + tanhf(0.7978845608028654f * (x + 0.044715f * x3)));
}

// ---------------- tiled GEMM 128x64 + epilogue ----------------
__global__ __launch_bounds__(256) void gemm_epi(
    const float* __restrict__ A, const float* __restrict__ W, float* __restrict__ C,
    int M, int K, int N, const float* __restrict__ res, int resMod,
    const float* __restrict__ bias, int doGelu)
{
    __shared__ float As[16][136];
    __shared__ float Bs[16][64];
    int t = threadIdx.x;
    int tx = t & 15, ty = t >> 4;
    int row0 = blockIdx.y * 128, col0 = blockIdx.x * 64;
    float acc[8][4] = {};
    int br = t >> 4, bc = (t & 15) * 4;
    for (int k0 = 0; k0 < K; k0 += 16) {
#pragma unroll
        for (int i = 0; i < 2; i++) {
            int s = t + i * 256;
            int r = s >> 2, c4 = (s & 3) * 4;
            float4 a4 = *(const float4*)(A + (size_t)(row0 + r) * K + k0 + c4);
            As[c4 + 0][r] = a4.x; As[c4 + 1][r] = a4.y;
            As[c4 + 2][r] = a4.z; As[c4 + 3][r] = a4.w;
        }
        *(float4*)&Bs[br][bc] = *(const float4*)(W + (size_t)(k0 + br) * N + col0 + bc);
        __syncthreads();
#pragma unroll
        for (int kk = 0; kk < 16; kk++) {
            float4 a0 = *(const float4*)&As[kk][ty * 8];
            float4 a1 = *(const float4*)&As[kk][ty * 8 + 4];
            float4 bv = *(const float4*)&Bs[kk][tx * 4];
            acc[0][0] += a0.x * bv.x; acc[0][1] += a0.x * bv.y; acc[0][2] += a0.x * bv.z; acc[0][3] += a0.x * bv.w;
            acc[1][0] += a0.y * bv.x; acc[1][1] += a0.y * bv.y; acc[1][2] += a0.y * bv.z; acc[1][3] += a0.y * bv.w;
            acc[2][0] += a0.z * bv.x; acc[2][1] += a0.z * bv.y; acc[2][2] += a0.z * bv.z; acc[2][3] += a0.z * bv.w;
            acc[3][0] += a0.w * bv.x; acc[3][1] += a0.w * bv.y; acc[3][2] += a0.w * bv.z; acc[3][3] += a0.w * bv.w;
            acc[4][0] += a1.x * bv.x; acc[4][1] += a1.x * bv.y; acc[4][2] += a1.x * bv.z; acc[4][3] += a1.x * bv.w;
            acc[5][0] += a1.y * bv.x; acc[5][1] += a1.y * bv.y; acc[5][2] += a1.y * bv.z; acc[5][3] += a1.y * bv.w;
            acc[6][0] += a1.z * bv.x; acc[6][1] += a1.z * bv.y; acc[6][2] += a1.z * bv.z; acc[6][3] += a1.z * bv.w;
            acc[7][0] += a1.w * bv.x; acc[7][1] += a1.w * bv.y; acc[7][2] += a1.w * bv.z; acc[7][3] += a1.w * bv.w;
        }
        __syncthreads();
    }
#pragma unroll
    for (int i = 0; i < 8; i++) {
        int r = row0 + ty * 8 + i;
#pragma unroll
        for (int j = 0; j < 4; j++) {
            int c = col0 + tx * 4 + j;
            float v = acc[i][j];
            if (bias) v += bias[c];
            if (doGelu) v = gelu_f(v);
            if (res) v += res[(size_t)(r % resMod) * N + c];
            C[(size_t)r * N + c] = v;
        }
    }
}

// ---------------- fused: all three table projections (z selects table) ----------------
__global__ __launch_bounds__(256) void gemm_all(
    const float* __restrict__ A0, const float* __restrict__ A1, const float* __restrict__ A2,
    const float* __restrict__ W,
    float* __restrict__ C0, float* __restrict__ C1, float* __restrict__ C2)
{
    int z = blockIdx.z;
    const float* A; float* C; int ymax;
    if (z == 0) { A = A0; C = C0; ymax = 32; }
    else if (z == 1) { A = A1; C = C1; ymax = 8; }
    else { A = A2; C = C2; ymax = 2; }
    if (blockIdx.y >= ymax) return;
    const int K = 256, N = 512;
    __shared__ float As[16][136];
    __shared__ float Bs[16][64];
    int t = threadIdx.x;
    int tx = t & 15, ty = t >> 4;
    int row0 = blockIdx.y * 128, col0 = blockIdx.x * 64;
    float acc[8][4] = {};
    int br = t >> 4, bc = (t & 15) * 4;
    for (int k0 = 0; k0 < K; k0 += 16) {
#pragma unroll
        for (int i = 0; i < 2; i++) {
            int s = t + i * 256;
            int r = s >> 2, c4 = (s & 3) * 4;
            float4 a4 = *(const float4*)(A + (size_t)(row0 + r) * K + k0 + c4);
            As[c4 + 0][r] = a4.x; As[c4 + 1][r] = a4.y;
            As[c4 + 2][r] = a4.z; As[c4 + 3][r] = a4.w;
        }
        *(float4*)&Bs[br][bc] = *(const float4*)(W + (size_t)(k0 + br) * N + col0 + bc);
        __syncthreads();
#pragma unroll
        for (int kk = 0; kk < 16; kk++) {
            float4 a0 = *(const float4*)&As[kk][ty * 8];
            float4 a1 = *(const float4*)&As[kk][ty * 8 + 4];
            float4 bv = *(const float4*)&Bs[kk][tx * 4];
            acc[0][0] += a0.x * bv.x; acc[0][1] += a0.x * bv.y; acc[0][2] += a0.x * bv.z; acc[0][3] += a0.x * bv.w;
            acc[1][0] += a0.y * bv.x; acc[1][1] += a0.y * bv.y; acc[1][2] += a0.y * bv.z; acc[1][3] += a0.y * bv.w;
            acc[2][0] += a0.z * bv.x; acc[2][1] += a0.z * bv.y; acc[2][2] += a0.z * bv.z; acc[2][3] += a0.z * bv.w;
            acc[3][0] += a0.w * bv.x; acc[3][1] += a0.w * bv.y; acc[3][2] += a0.w * bv.z; acc[3][3] += a0.w * bv.w;
            acc[4][0] += a1.x * bv.x; acc[4][1] += a1.x * bv.y; acc[4][2] += a1.x * bv.z; acc[4][3] += a1.x * bv.w;
            acc[5][0] += a1.y * bv.x; acc[5][1] += a1.y * bv.y; acc[5][2] += a1.y * bv.z; acc[5][3] += a1.y * bv.w;
            acc[6][0] += a1.z * bv.x; acc[6][1] += a1.z * bv.y; acc[6][2] += a1.z * bv.z; acc[6][3] += a1.z * bv.w;
            acc[7][0] += a1.w * bv.x; acc[7][1] += a1.w * bv.y; acc[7][2] += a1.w * bv.z; acc[7][3] += a1.w * bv.w;
        }
        __syncthreads();
    }
#pragma unroll
    for (int i = 0; i < 8; i++) {
        int r = row0 + ty * 8 + i;
#pragma unroll
        for (int j = 0; j < 4; j++)
            C[(size_t)r * 512 + col0 + tx * 4 + j] = acc[i][j];
    }
}

// ---------------- sort step 1: per-32-event-subgroup batch histogram ----------------
__global__ void hist32_kernel(const int* __restrict__ bidx, int* __restrict__ cnt, int E)
{
    int t = threadIdx.x;
    int e = blockIdx.x * 256 + t;
    int w = t >> 5, lane = t & 31;
    int b = (e < E) ? bidx[e] : -1;
    int g = blockIdx.x * 8 + w;
#pragma unroll
    for (int bb = 0; bb < 16; bb++) {
        unsigned m = __ballot_sync(0xffffffffu, b == bb);
        if (lane == 0) cnt[g * 16 + bb] = __popc(m);
    }
}

// ---------------- sort step 2: offsets (1 block, 512 thr) + Wkv colsum fused ----------------
__global__ void scanoffs_kernel(const int* __restrict__ cnt, int G32,
                                const float* __restrict__ Wkv, float* __restrict__ CS,
                                int* __restrict__ base, int* __restrict__ bo, int E)
{
    int t = threadIdx.x;
    // colsum of Wkv (independent work)
    {
        float s = 0.f;
#pragma unroll 8
        for (int k = 0; k < 256; k++) s += Wkv[k * 512 + t];
        CS[t] = s;
    }
    __shared__ int tot[16];
    int b = t >> 5, lane = t & 31;
    int seg = (G32 + 31) / 32;
    int g0 = lane * seg, g1 = g0 + seg; if (g1 > G32) g1 = G32; if (g0 > G32) g0 = G32;
    int s = 0;
    for (int g = g0; g < g1; g++) s += cnt[g * 16 + b];
    int incl = s;
#pragma unroll
    for (int o = 1; o < 32; o <<= 1) {
        int v = __shfl_up_sync(0xffffffffu, incl, o);
        if (lane >= o) incl += v;
    }
    int run = incl - s;  // exclusive
    for (int g = g0; g < g1; g++) {
        int c = cnt[g * 16 + b];
        base[g * 16 + b] = run;
        run += c;
    }
    if (lane == 31) tot[b] = incl;
    __syncthreads();
    if (t == 0) {
        int acc = 0;
        for (int bb = 0; bb < 16; bb++) { bo[bb] = acc; acc += tot[bb]; }
        bo[16] = acc;
    }
}

// ---------------- per-event KV (writes rows batch-sorted) ----------------
__global__ __launch_bounds__(256) void event_kv_kernel(
    const int* __restrict__ nid, const int* __restrict__ tbi, const int* __restrict__ vli,
    const int* __restrict__ bidx,
    const float* __restrict__ nemb, const float* __restrict__ temb, const float* __restrict__ vemb,
    const float* __restrict__ nW, const float* __restrict__ tW, const float* __restrict__ vW,
    const float* __restrict__ colsum,
    const int* __restrict__ base32, const int* __restrict__ bo,
    float* __restrict__ KV, int E)
{
    __shared__ float sMean[32], sInv[32];
    __shared__ int sNi[32], sTi[32], sVi[32], sPos[32];
    int t = threadIdx.x;
    int g = blockIdx.x;
    int basee = g * 32;
    // warp 0: sorted positions via stable in-warp rank
    if (t < 32) {
        int e = basee + t;
        int b = (e < E) ? bidx[e] : -1;
        int rank = 0;
#pragma unroll
        for (int bb = 0; bb < 16; bb++) {
            unsigned m = __ballot_sync(0xffffffffu, b == bb);
            if (b == bb) rank = __popc(m & ((1u << t) - 1u));
        }
        if (e < E) sPos[t] = bo[b] + base32[g * 16 + b] + rank;
    }
    int le = t >> 3, g8 = t & 7;
    int e = basee + le;
    float s = 0.f, sq = 0.f;
    if (e < E) {
        int ni = nid[e], ti = tbi[e], vi = vli[e];
        if (g8 == 0) { sNi[le] = ni; sTi[le] = ti; sVi[le] = vi; }
        const float* np = nemb + (size_t)ni * 256;
        const float* tp = temb + (size_t)ti * 256;
        const float* vp = vemb + (size_t)vi * 256;
#pragma unroll
        for (int i = 0; i < 8; i++) {
            int d = g8 * 32 + i * 4;
            float4 a = *(const float4*)(np + d);
            float4 bq = *(const float4*)(tp + d);
            float4 c = *(const float4*)(vp + d);
            float x0 = a.x + bq.x + c.x, x1 = a.y + bq.y + c.y;
            float x2 = a.z + bq.z + c.z, x3 = a.w + bq.w + c.w;
            s += x0 + x1 + x2 + x3;
            sq += x0 * x0 + x1 * x1 + x2 * x2 + x3 * x3;
        }
    }
    s += __shfl_xor_sync(0xffffffffu, s, 1);
    s += __shfl_xor_sync(0xffffffffu, s, 2);
    s += __shfl_xor_sync(0xffffffffu, s, 4);
    sq += __shfl_xor_sync(0xffffffffu, sq, 1);
    sq += __shfl_xor_sync(0xffffffffu, sq, 2);
    sq += __shfl_xor_sync(0xffffffffu, sq, 4);
    if (g8 == 0 && e < E) {
        float mean = s * (1.0f / 256.0f);
        float var = sq * (1.0f / 256.0f) - mean * mean;
        sMean[le] = mean;
        sInv[le] = rsqrtf(var + 1e-5f);
    }
    __syncthreads();
    int nE = E - basee; if (nE > 32) nE = 32;
    float cs0 = colsum[t], cs1 = colsum[t + 256];
#pragma unroll 4
    for (int ee = 0; ee < nE; ee++) {
        int ni = sNi[ee], ti = sTi[ee], vi = sVi[ee];
        float inv = sInv[ee];
        float mi = sMean[ee] * inv;
        float p0 = nW[(size_t)ni * 512 + t] + tW[(size_t)ti * 512 + t] + vW[(size_t)vi * 512 + t];
        float p1 = nW[(size_t)ni * 512 + 256 + t] + tW[(size_t)ti * 512 + 256 + t] + vW[(size_t)vi * 512 + 256 + t];
        size_t row = (size_t)sPos[ee];
        KV[row * 512 + t] = inv * p0 - mi * cs0;
        KV[row * 512 + 256 + t] = inv * p1 - mi * cs1;
    }
}

// ---------------- LayerNorm ----------------
__global__ void ln_kernel(const float* __restrict__ X, float* __restrict__ Y,
                          const float* __restrict__ w, const float* __restrict__ b, int rows)
{
    int row = blockIdx.x * 8 + (threadIdx.x >> 5);
    int lane = threadIdx.x & 31;
    if (row >= rows) return;
    const float* x = X + (size_t)row * 256;
    float v[8]; float s = 0.f, sq = 0.f;
#pragma unroll
    for (int i = 0; i < 8; i++) { v[i] = x[lane + 32 * i]; s += v[i]; sq += v[i] * v[i]; }
#pragma unroll
    for (int o = 16; o > 0; o >>= 1) {
        s += __shfl_xor_sync(0xffffffffu, s, o);
        sq += __shfl_xor_sync(0xffffffffu, sq, o);
    }
    float mean = s * (1.0f / 256.0f);
    float var = sq * (1.0f / 256.0f) - mean * mean;
    float inv = rsqrtf(var + 1e-5f);
    float* y = Y + (size_t)row * 256;
#pragma unroll
    for (int i = 0; i < 8; i++) {
        int d = lane + 32 * i;
        float o = (v[i] - mean) * inv;
        if (w) o = o * w[d] + b[d];
        y[d] = o;
    }
}

// ---------------- cross-attn Q ----------------
__global__ void qc_kernel(const float* __restrict__ lnlat, const float* __restrict__ Wq,
                          float* __restrict__ qout)
{
    int l = blockIdx.x;
    int c = threadIdx.x;
    float s = 0.f;
#pragma unroll 8
    for (int k = 0; k < 256; k++) s += lnlat[l * 256 + k] * Wq[k * 256 + c];
    int h = c >> 5, dh = c & 31;
    qout[(h * 64 + l) * 32 + dh] = s * 0.17677669529663689f;
}

// ---------------- dense sorted cross-attn scan ----------------
// grid (NCHUNK, 16); 512 threads = 8 heads x 64 latents; 16-event smem tiles
__global__ __launch_bounds__(512) void attn_scan_sorted(
    const float* __restrict__ KV, const float* __restrict__ qg,
    const int* __restrict__ bo,
    float* __restrict__ pO, float* __restrict__ pZ)
{
    __shared__ float sKV[16 * 512];
    int t = threadIdx.x;
    int h = t >> 6, l = t & 63;
    int b = blockIdx.y, chunk = blockIdx.x;
    int start = bo[b], end = bo[b + 1];
    int cntb = end - start;
    int len = (cntb + NCHUNK - 1) / NCHUNK;
    int s0 = start + chunk * len;
    int s1 = s0 + len; if (s1 > end) s1 = end;

    float q[32];
    {
        const float4* qp = (const float4*)(qg + (h * 64 + l) * 32);
#pragma unroll
        for (int j = 0; j < 8; j++) {
            float4 v = qp[j];
            q[j * 4 + 0] = v.x; q[j * 4 + 1] = v.y; q[j * 4 + 2] = v.z; q[j * 4 + 3] = v.w;
        }
    }
    float accO[32];
#pragma unroll
    for (int j = 0; j < 32; j++) accO[j] = 0.f;
    float z = 0.f;

    const float4* KV4 = (const float4*)KV;
    for (int tile = s0; tile < s1; tile += 16) {
        int nt = s1 - tile; if (nt > 16) nt = 16;
        __syncthreads();
        int nq = nt * 128;  // float4 count
        float4* d4 = (float4*)sKV;
        for (int i = t; i < nq; i += 512) d4[i] = KV4[(size_t)tile * 128 + i];
        __syncthreads();
        for (int e = 0; e < nt; e++) {
            const float4* kp4 = (const float4*)(sKV + e * 512 + h * 32);
            float sc = 0.f;
#pragma unroll
            for (int j = 0; j < 8; j++) {
                float4 k4 = kp4[j];
                sc += q[j * 4 + 0] * k4.x + q[j * 4 + 1] * k4.y
                    + q[j * 4 + 2] * k4.z + q[j * 4 + 3] * k4.w;
            }
            float p = __expf(sc);
            z += p;
            const float4* vp4 = kp4 + 64;  // +256 floats
#pragma unroll
            for (int j = 0; j < 8; j++) {
                float4 v4 = vp4[j];
                accO[j * 4 + 0] += p * v4.x; accO[j * 4 + 1] += p * v4.y;
                accO[j * 4 + 2] += p * v4.z; accO[j * 4 + 3] += p * v4.w;
            }
        }
    }
    size_t pb = (size_t)((b * 8 + h) * NCHUNK + chunk);
    float4* po4 = (float4*)(pO + pb * 2048 + l * 32);
#pragma unroll
    for (int j = 0; j < 8; j++)
        po4[j] = make_float4(accO[j * 4], accO[j * 4 + 1], accO[j * 4 + 2], accO[j * 4 + 3]);
    pZ[pb * 64 + l] = z;
}

// ---------------- combine chunk partials ----------------
__global__ void attn_combine_kernel(const float* __restrict__ pO, const float* __restrict__ pZ,
                                    float* __restrict__ attn)
{
    int bh = blockIdx.x;
    int b = bh >> 3, h = bh & 7;
    int t = threadIdx.x;
    __shared__ float sz[64];
    if (t < 64) {
        float zz = 0.f;
        for (int c = 0; c < NCHUNK; c++) zz += pZ[((size_t)bh * NCHUNK + c) * 64 + t];
        sz[t] = 1.0f / zz;
    }
    __syncthreads();
    for (int i = t; i < 2048; i += 256) {
        int l = i >> 5, d = i & 31;
        float s = 0.f;
        for (int c = 0; c < NCHUNK; c++) s += pO[((size_t)bh * NCHUNK + c) * 2048 + i];
        attn[(size_t)(b * 64 + l) * 256 + h * 32 + d] = s * sz[l];
    }
}

// ---------------- self-attention over latents ----------------
__global__ __launch_bounds__(256) void self_attn_kernel(const float* __restrict__ qkv,
                                                        float* __restrict__ out)
{
    int b = blockIdx.x, h = blockIdx.y;
    __shared__ float sk[2048], sv[2048];
    int t = threadIdx.x;
    for (int i = t; i < 2048; i += 256) {
        int key = i >> 5, d = i & 31;
        size_t rowb = (size_t)(b * 64 + key) * 768;
        sk[i] = qkv[rowb + 256 + h * 32 + d];
        sv[i] = qkv[rowb + 512 + h * 32 + d];
    }
    __syncthreads();
    int ql = t >> 2, r = t & 3;
    const float* qp = qkv + (size_t)(b * 64 + ql) * 768 + h * 32 + r * 8;
    float qv[8];
#pragma unroll
    for (int j = 0; j < 8; j++) qv[j] = qp[j] * 0.17677669529663689f;
    float z = 0.f;
    for (int key = 0; key < 64; key++) {
        float part = 0.f;
#pragma unroll
        for (int j = 0; j < 8; j++) part += qv[j] * sk[key * 32 + r * 8 + j];
        part += __shfl_xor_sync(0xffffffffu, part, 1);
        part += __shfl_xor_sync(0xffffffffu, part, 2);
        z += __expf(part);
    }
    float o[8] = {0.f, 0.f, 0.f, 0.f, 0.f, 0.f, 0.f, 0.f};
    for (int key = 0; key < 64; key++) {
        float part = 0.f;
#pragma unroll
        for (int j = 0; j < 8; j++) part += qv[j] * sk[key * 32 + r * 8 + j];
        part += __shfl_xor_sync(0xffffffffu, part, 1);
        part += __shfl_xor_sync(0xffffffffu, part, 2);
        float p = __expf(part);
#pragma unroll
        for (int j = 0; j < 8; j++) o[j] += p * sv[key * 32 + r * 8 + j];
    }
    float invz = 1.0f / z;
#pragma unroll
    for (int j = 0; j < 8; j++)
        out[(size_t)(b * 64 + ql) * 256 + h * 32 + r * 8 + j] = o[j] * invz;
}

// ---------------- behavior query ----------------
__global__ void qb_kernel(const float* __restrict__ bhq, const float* __restrict__ wq,
                          float* __restrict__ qb)
{
    int t = threadIdx.x;
    int be = t >> 8, c = t & 255;
    float s = 0.f;
#pragma unroll 8
    for (int k = 0; k < 256; k++) s += bhq[be * 256 + k] * wq[k * 256 + c];
    int h = c >> 5, dh = c & 31;
    qb[(h * 2 + be) * 32 + dh] = s * 0.17677669529663689f;
}

// ---------------- behavior attention ----------------
__global__ void bh_attn_kernel(const float* __restrict__ kvb, const float* __restrict__ qb,
                               float* __restrict__ bo)
{
    int b = blockIdx.x, h = blockIdx.y;
    __shared__ float sk[2048], sv[2048];
    int t = threadIdx.x;
    for (int i = t; i < 2048; i += 64) {
        int key = i >> 5, d = i & 31;
        size_t rowb = (size_t)(b * 64 + key) * 512;
        sk[i] = kvb[rowb + h * 32 + d];
        sv[i] = kvb[rowb + 256 + h * 32 + d];
    }
    __syncthreads();
    int be = t >> 5, d = t & 31;
    float q[32];
#pragma unroll
    for (int j = 0; j < 32; j++) q[j] = qb[(h * 2 + be) * 32 + j];
    float z = 0.f, o = 0.f;
    for (int key = 0; key < 64; key++) {
        float s = 0.f;
#pragma unroll
        for (int j = 0; j < 32; j++) s += q[j] * sk[key * 32 + j];
        float p = __expf(s);
        z += p;
        o += p * sv[key * 32 + d];
    }
    bo[(size_t)(b * 2 + be) * 256 + h * 32 + d] = o / z;
}

// ---------------- behavior output ----------------
__global__ void bh_out_kernel(const float* __restrict__ bo, const float* __restrict__ wo,
                              float* __restrict__ outBeh)
{
    int t = threadIdx.x;
    int row = t >> 5, lane = t & 31;
    float s = 0.f;
#pragma unroll
    for (int i = 0; i < 8; i++) s += bo[row * 256 + lane + 32 * i] * wo[lane + 32 * i];
#pragma unroll
    for (int o = 16; o > 0; o >>= 1) s += __shfl_xor_sync(0xffffffffu, s, o);
    if (lane == 0) outBeh[row] = s;
}

// ---------------- mean over latents ----------------
__global__ void mean_kernel(const float* __restrict__ lat, float* __restrict__ mn)
{
    int b = blockIdx.x, d = threadIdx.x;
    float s = 0.f;
#pragma unroll 8
    for (int l = 0; l < 64; l++) s += lat[(size_t)(b * 64 + l) * 256 + d];
    mn[b * 256 + d] = s * (1.0f / 64.0f);
}

// ---------------- logits ----------------
__global__ void logits_kernel(const float* __restrict__ mn, const float* __restrict__ spw,
                              const float* __restrict__ spb, float* __restrict__ out)
{
    int t = threadIdx.x;
    int b = t >> 6, s = t & 63;
    float acc = spb[s];
#pragma unroll 8
    for (int k = 0; k < 256; k++) acc += mn[b * 256 + k] * spw[k * 64 + s];
    out[b * 64 + s] = acc;
}

// ---------------- host launcher ----------------
extern "C" void kernel_launch(void* const* d_in, const int* in_sizes, int n_in,
                              void* d_out, int out_size)
{
    int ib, wb;
    if (in_sizes[0] == in_sizes[1] && in_sizes[1] == in_sizes[2] && in_sizes[2] == in_sizes[3]) {
        ib = 0; wb = n_in - 21;
    } else {
        wb = 0; ib = 21;
    }
    const int* nid  = (const int*)d_in[ib + 0];
    const int* tbi  = (const int*)d_in[ib + 1];
    const int* vli  = (const int*)d_in[ib + 2];
    const int* bidx = (const int*)d_in[ib + 3];
    int E = in_sizes[ib];
    if (E > EVCAP) E = EVCAP;

    const float* nemb    = (const float*)d_in[wb + 0];
    const float* temb    = (const float*)d_in[wb + 1];
    const float* vemb    = (const float*)d_in[wb + 2];
    const float* lat0    = (const float*)d_in[wb + 3];
    const float* Wq_c    = (const float*)d_in[wb + 4];
    const float* Wkv_c   = (const float*)d_in[wb + 5];
    const float* Wo_c    = (const float*)d_in[wb + 6];
    const float* W1_c    = (const float*)d_in[wb + 7];
    const float* W2_c    = (const float*)d_in[wb + 8];
    const float* Wqkv_s  = (const float*)d_in[wb + 9];
    const float* Wo_s    = (const float*)d_in[wb + 10];
    const float* W1_s    = (const float*)d_in[wb + 11];
    const float* W2_s    = (const float*)d_in[wb + 12];
    const float* bh_query = (const float*)d_in[wb + 13];
    const float* bh_wq   = (const float*)d_in[wb + 14];
    const float* bh_wkv  = (const float*)d_in[wb + 15];
    const float* bh_wo   = (const float*)d_in[wb + 16];
    const float* bh_ln_w = (const float*)d_in[wb + 17];
    const float* bh_ln_b = (const float*)d_in[wb + 18];
    const float* sp_w    = (const float*)d_in[wb + 19];
    const float* sp_b    = (const float*)d_in[wb + 20];

    float* buf = nullptr;
    cudaGetSymbolAddress((void**)&buf, g_buf);
    int* ibuf = nullptr;
    cudaGetSymbolAddress((void**)&ibuf, g_ibuf);

    float* KV   = buf + O_KV;
    float* nW   = buf + O_NW;
    float* tW   = buf + O_TW;
    float* vW   = buf + O_VW;
    float* CS   = buf + O_CS;
    float* Qg   = buf + O_Q;
    float* PO   = buf + O_PO;
    float* PZ   = buf + O_PZ;
    float* LAT  = buf + O_LAT;
    float* LNB  = buf + O_LN;
    float* T1   = buf + O_T1;
    float* T2   = buf + O_T2;
    float* AT   = buf + O_AT;
    float* XB   = buf + O_XB;
    float* KB   = buf + O_KB;
    float* QB   = buf + O_QB;
    float* BO   = buf + O_BO2;
    float* MN   = buf + O_MEAN;
    int* CNT  = ibuf + I_CNT;
    int* BASE = ibuf + I_BASE;
    int* BOFF = ibuf + I_BO;
    float* out = (float*)d_out;

    int G256 = (E + 255) / 256;
    int G32  = (E + 31) / 32;

    // [0] histogram, [1] offsets+colsum, [2] fused table GEMMs, [3] event KV (profiled slot)
    hist32_kernel<<<G256, 256>>>(bidx, CNT, E);
    scanoffs_kernel<<<1, 512>>>(CNT, G32, Wkv_c, CS, BASE, BOFF, E);
    gemm_all<<<dim3(8, 32, 3), 256>>>(nemb, temb, vemb, Wkv_c, nW, tW, vW);
    event_kv_kernel<<<G32, 256>>>(nid, tbi, vli, bidx, nemb, temb, vemb,
                                  nW, tW, vW, CS, BASE, BOFF, KV, E);

    // Cross-attention
    ln_kernel<<<8, 256>>>(lat0, LNB, nullptr, nullptr, 64);
    qc_kernel<<<64, 256>>>(LNB, Wq_c, Qg);
    attn_scan_sorted<<<dim3(NCHUNK, 16), 512>>>(KV, Qg, BOFF, PO, PZ);
    attn_combine_kernel<<<128, 256>>>(PO, PZ, AT);

    // lat = lat_init + attn @ Wo_c
    gemm_epi<<<dim3(4, 8), 256>>>(AT, Wo_c, LAT, 1024, 256, 256, lat0, 64, nullptr, 0);
    // lat += gelu(ln(lat) @ W1_c) @ W2_c
    ln_kernel<<<128, 256>>>(LAT, LNB, nullptr, nullptr, 1024);
    gemm_epi<<<dim3(16, 8), 256>>>(LNB, W1_c, T1, 1024, 256, 1024, nullptr, 1, nullptr, 1);
    gemm_epi<<<dim3(4, 8), 256>>>(T1, W2_c, LAT, 1024, 1024, 256, LAT, 1024, nullptr, 0);

    // Self-attention layers
    for (int i = 0; i < 2; i++) {
        ln_kernel<<<128, 256>>>(LAT, LNB, nullptr, nullptr, 1024);
        gemm_epi<<<dim3(12, 8), 256>>>(LNB, Wqkv_s + (size_t)i * 256 * 768, T2, 1024, 256, 768,
                                       nullptr, 1, nullptr, 0);
        self_attn_kernel<<<dim3(16, 8), 256>>>(T2, AT);
        gemm_epi<<<dim3(4, 8), 256>>>(AT, Wo_s + (size_t)i * 256 * 256, LAT, 1024, 256, 256,
                                      LAT, 1024, nullptr, 0);
        ln_kernel<<<128, 256>>>(LAT, LNB, nullptr, nullptr, 1024);
        gemm_epi<<<dim3(16, 8), 256>>>(LNB, W1_s + (size_t)i * 256 * 1024, T1, 1024, 256, 1024,
                                       nullptr, 1, nullptr, 1);
        gemm_epi<<<dim3(4, 8), 256>>>(T1, W2_s + (size_t)i * 1024 * 256, LAT, 1024, 1024, 256,
                                      LAT, 1024, nullptr, 0);
    }

    // Behavior decoder
    ln_kernel<<<128, 256>>>(LAT, XB, bh_ln_w, bh_ln_b, 1024);
    qb_kernel<<<1, 512>>>(bh_query, bh_wq, QB);
    gemm_epi<<<dim3(8, 8), 256>>>(XB, bh_wkv, KB, 1024, 256, 512, nullptr, 1, nullptr, 0);
    bh_attn_kernel<<<dim3(16, 8), 64>>>(KB, QB, BO);
    bh_out_kernel<<<1, 1024>>>(BO, bh_wo, out);

    // Spike head
    mean_kernel<<<16, 256>>>(LAT, MN);
    logits_kernel<<<1, 1024>>>(MN, sp_w, sp_b, out + 32);
}

// round 12
// speedup vs baseline: 1.5922x; 1.0852x over previous
#include <cuda_runtime.h>
#include <math.h>
#include <stdint.h>

// ---------------- constants ----------------
#define NCHUNK 32
#define EVCAP  204800

// ---------------- float scratch ----------------
static constexpr size_t O_KV = 0;                                   // (EVCAP,512) sorted k|v
static constexpr size_t O_NW = O_KV + (size_t)EVCAP * 512;          // 4096x512
static constexpr size_t O_TW = O_NW + (size_t)4096 * 512;           // 1024x512
static constexpr size_t O_VW = O_TW + (size_t)1024 * 512;           // 256x512
static constexpr size_t O_CS = O_VW + (size_t)256 * 512;            // 512 colsum
static constexpr size_t O_Q  = O_CS + 512;                          // (H,64,32)
static constexpr size_t O_PO = O_Q + 8 * 64 * 32;                   // (B,H,NCHUNK,64,32)
static constexpr size_t O_PZ = O_PO + (size_t)16 * 8 * NCHUNK * 64 * 32;
static constexpr size_t O_LAT = O_PZ + (size_t)16 * 8 * NCHUNK * 64;
static constexpr size_t O_LN  = O_LAT + 1024 * 256;
static constexpr size_t O_T1  = O_LN + 1024 * 256;
static constexpr size_t O_T2  = O_T1 + 1024 * 1024;
static constexpr size_t O_AT  = O_T2 + 1024 * 768;
static constexpr size_t O_XB  = O_AT + 1024 * 256;
static constexpr size_t O_KB  = O_XB + 1024 * 256;
static constexpr size_t O_QB  = O_KB + 1024 * 512;
static constexpr size_t O_BO2 = O_QB + 512;
static constexpr size_t O_MEAN = O_BO2 + 16 * 2 * 256;
static constexpr size_t SCRATCH_TOTAL = O_MEAN + 16 * 256;

__device__ float g_buf[SCRATCH_TOTAL];

// ---------------- int scratch (sorting) ----------------
static constexpr size_t I_CNT  = 0;            // 6400*16 per-32-subgroup counts
static constexpr size_t I_BASE = 102400;       // 6400*16 within-batch prefix
static constexpr size_t I_BO   = 204800;       // 17 batch offsets
__device__ int g_ibuf[204832];

__device__ __forceinline__ float gelu_f(float x) {
    float x3 = x * x * x;
    return 0.5f * x * (1.0f + tanhf(0.7978845608028654f * (x + 0.044715f * x3)));
}

// ---------------- tiled GEMM 64x64 + epilogue (occupancy-friendly) ----------------
// C(MxN) = A(MxK) @ W(KxN); optional bias[c], gelu, residual res[(r%resMod)*N + c]
// Requires M%64==0, N%64==0, K%16==0.
__global__ __launch_bounds__(256) void gemm_epi(
    const float* __restrict__ A, const float* __restrict__ W, float* __restrict__ C,
    int M, int K, int N, const float* __restrict__ res, int resMod,
    const float* __restrict__ bias, int doGelu)
{
    __shared__ float As[16][68];
    __shared__ float Bs[16][64];
    int t = threadIdx.x;
    int tx = t & 15, ty = t >> 4;
    int row0 = blockIdx.y * 64, col0 = blockIdx.x * 64;
    float acc[4][4] = {};
    int ar = t >> 2, ac = (t & 3) * 4;
    int br = t >> 4, bc = (t & 15) * 4;
    for (int k0 = 0; k0 < K; k0 += 16) {
        float4 a4 = *(const float4*)(A + (size_t)(row0 + ar) * K + k0 + ac);
        As[ac + 0][ar] = a4.x; As[ac + 1][ar] = a4.y;
        As[ac + 2][ar] = a4.z; As[ac + 3][ar] = a4.w;
        *(float4*)&Bs[br][bc] = *(const float4*)(W + (size_t)(k0 + br) * N + col0 + bc);
        __syncthreads();
#pragma unroll
        for (int kk = 0; kk < 16; kk++) {
            float4 av = *(const float4*)&As[kk][ty * 4];
            float4 bv = *(const float4*)&Bs[kk][tx * 4];
            acc[0][0] += av.x * bv.x; acc[0][1] += av.x * bv.y; acc[0][2] += av.x * bv.z; acc[0][3] += av.x * bv.w;
            acc[1][0] += av.y * bv.x; acc[1][1] += av.y * bv.y; acc[1][2] += av.y * bv.z; acc[1][3] += av.y * bv.w;
            acc[2][0] += av.z * bv.x; acc[2][1] += av.z * bv.y; acc[2][2] += av.z * bv.z; acc[2][3] += av.z * bv.w;
            acc[3][0] += av.w * bv.x; acc[3][1] += av.w * bv.y; acc[3][2] += av.w * bv.z; acc[3][3] += av.w * bv.w;
        }
        __syncthreads();
    }
#pragma unroll
    for (int i = 0; i < 4; i++) {
        int r = row0 + ty * 4 + i;
#pragma unroll
        for (int j = 0; j < 4; j++) {
            int c = col0 + tx * 4 + j;
            float v = acc[i][j];
            if (bias) v += bias[c];
            if (doGelu) v = gelu_f(v);
            if (res) v += res[(size_t)(r % resMod) * N + c];
            C[(size_t)r * N + c] = v;
        }
    }
}

// ---------------- fused: all three table projections, 64x64 tiles ----------------
__global__ __launch_bounds__(256) void gemm_all(
    const float* __restrict__ A0, const float* __restrict__ A1, const float* __restrict__ A2,
    const float* __restrict__ W,
    float* __restrict__ C0, float* __restrict__ C1, float* __restrict__ C2)
{
    int z = blockIdx.z;
    const float* A; float* C; int ymax;
    if (z == 0) { A = A0; C = C0; ymax = 64; }
    else if (z == 1) { A = A1; C = C1; ymax = 16; }
    else { A = A2; C = C2; ymax = 4; }
    if (blockIdx.y >= ymax) return;
    const int K = 256, N = 512;
    __shared__ float As[16][68];
    __shared__ float Bs[16][64];
    int t = threadIdx.x;
    int tx = t & 15, ty = t >> 4;
    int row0 = blockIdx.y * 64, col0 = blockIdx.x * 64;
    float acc[4][4] = {};
    int ar = t >> 2, ac = (t & 3) * 4;
    int br = t >> 4, bc = (t & 15) * 4;
    for (int k0 = 0; k0 < K; k0 += 16) {
        float4 a4 = *(const float4*)(A + (size_t)(row0 + ar) * K + k0 + ac);
        As[ac + 0][ar] = a4.x; As[ac + 1][ar] = a4.y;
        As[ac + 2][ar] = a4.z; As[ac + 3][ar] = a4.w;
        *(float4*)&Bs[br][bc] = *(const float4*)(W + (size_t)(k0 + br) * N + col0 + bc);
        __syncthreads();
#pragma unroll
        for (int kk = 0; kk < 16; kk++) {
            float4 av = *(const float4*)&As[kk][ty * 4];
            float4 bv = *(const float4*)&Bs[kk][tx * 4];
            acc[0][0] += av.x * bv.x; acc[0][1] += av.x * bv.y; acc[0][2] += av.x * bv.z; acc[0][3] += av.x * bv.w;
            acc[1][0] += av.y * bv.x; acc[1][1] += av.y * bv.y; acc[1][2] += av.y * bv.z; acc[1][3] += av.y * bv.w;
            acc[2][0] += av.z * bv.x; acc[2][1] += av.z * bv.y; acc[2][2] += av.z * bv.z; acc[2][3] += av.z * bv.w;
            acc[3][0] += av.w * bv.x; acc[3][1] += av.w * bv.y; acc[3][2] += av.w * bv.z; acc[3][3] += av.w * bv.w;
        }
        __syncthreads();
    }
#pragma unroll
    for (int i = 0; i < 4; i++) {
        int r = row0 + ty * 4 + i;
#pragma unroll
        for (int j = 0; j < 4; j++)
            C[(size_t)r * 512 + col0 + tx * 4 + j] = acc[i][j];
    }
}

// ---------------- sort step 1: per-32-event-subgroup batch histogram ----------------
__global__ void hist32_kernel(const int* __restrict__ bidx, int* __restrict__ cnt, int E)
{
    int t = threadIdx.x;
    int e = blockIdx.x * 256 + t;
    int w = t >> 5, lane = t & 31;
    int b = (e < E) ? bidx[e] : -1;
    int g = blockIdx.x * 8 + w;
#pragma unroll
    for (int bb = 0; bb < 16; bb++) {
        unsigned m = __ballot_sync(0xffffffffu, b == bb);
        if (lane == 0) cnt[g * 16 + bb] = __popc(m);
    }
}

// ---------------- sort step 2: offsets (1 block, 512 thr) + Wkv colsum fused ----------------
__global__ void scanoffs_kernel(const int* __restrict__ cnt, int G32,
                                const float* __restrict__ Wkv, float* __restrict__ CS,
                                int* __restrict__ base, int* __restrict__ bo, int E)
{
    int t = threadIdx.x;
    {
        float s = 0.f;
#pragma unroll 8
        for (int k = 0; k < 256; k++) s += Wkv[k * 512 + t];
        CS[t] = s;
    }
    __shared__ int tot[16];
    int b = t >> 5, lane = t & 31;
    int seg = (G32 + 31) / 32;
    int g0 = lane * seg, g1 = g0 + seg; if (g1 > G32) g1 = G32; if (g0 > G32) g0 = G32;
    int s = 0;
    for (int g = g0; g < g1; g++) s += cnt[g * 16 + b];
    int incl = s;
#pragma unroll
    for (int o = 1; o < 32; o <<= 1) {
        int v = __shfl_up_sync(0xffffffffu, incl, o);
        if (lane >= o) incl += v;
    }
    int run = incl - s;  // exclusive
    for (int g = g0; g < g1; g++) {
        int c = cnt[g * 16 + b];
        base[g * 16 + b] = run;
        run += c;
    }
    if (lane == 31) tot[b] = incl;
    __syncthreads();
    if (t == 0) {
        int acc = 0;
        for (int bb = 0; bb < 16; bb++) { bo[bb] = acc; acc += tot[bb]; }
        bo[16] = acc;
    }
}

// ---------------- per-event KV (batch-sorted, float2-vectorized hot loop) ----------------
__global__ __launch_bounds__(256) void event_kv_kernel(
    const int* __restrict__ nid, const int* __restrict__ tbi, const int* __restrict__ vli,
    const int* __restrict__ bidx,
    const float* __restrict__ nemb, const float* __restrict__ temb, const float* __restrict__ vemb,
    const float* __restrict__ nW, const float* __restrict__ tW, const float* __restrict__ vW,
    const float* __restrict__ colsum,
    const int* __restrict__ base32, const int* __restrict__ bo,
    float* __restrict__ KV, int E)
{
    __shared__ float sMean[32], sInv[32];
    __shared__ int sNi[32], sTi[32], sVi[32], sPos[32];
    int t = threadIdx.x;
    int g = blockIdx.x;
    int basee = g * 32;
    // warp 0: sorted positions via stable in-warp rank
    if (t < 32) {
        int e = basee + t;
        int b = (e < E) ? bidx[e] : -1;
        int rank = 0;
#pragma unroll
        for (int bb = 0; bb < 16; bb++) {
            unsigned m = __ballot_sync(0xffffffffu, b == bb);
            if (b == bb) rank = __popc(m & ((1u << t) - 1u));
        }
        if (e < E) sPos[t] = bo[b] + base32[g * 16 + b] + rank;
    }
    int le = t >> 3, g8 = t & 7;
    int e = basee + le;
    float s = 0.f, sq = 0.f;
    if (e < E) {
        int ni = nid[e], ti = tbi[e], vi = vli[e];
        if (g8 == 0) { sNi[le] = ni; sTi[le] = ti; sVi[le] = vi; }
        const float* np = nemb + (size_t)ni * 256;
        const float* tp = temb + (size_t)ti * 256;
        const float* vp = vemb + (size_t)vi * 256;
#pragma unroll
        for (int i = 0; i < 8; i++) {
            int d = g8 * 32 + i * 4;
            float4 a = *(const float4*)(np + d);
            float4 bq = *(const float4*)(tp + d);
            float4 c = *(const float4*)(vp + d);
            float x0 = a.x + bq.x + c.x, x1 = a.y + bq.y + c.y;
            float x2 = a.z + bq.z + c.z, x3 = a.w + bq.w + c.w;
            s += x0 + x1 + x2 + x3;
            sq += x0 * x0 + x1 * x1 + x2 * x2 + x3 * x3;
        }
    }
    s += __shfl_xor_sync(0xffffffffu, s, 1);
    s += __shfl_xor_sync(0xffffffffu, s, 2);
    s += __shfl_xor_sync(0xffffffffu, s, 4);
    sq += __shfl_xor_sync(0xffffffffu, sq, 1);
    sq += __shfl_xor_sync(0xffffffffu, sq, 2);
    sq += __shfl_xor_sync(0xffffffffu, sq, 4);
    if (g8 == 0 && e < E) {
        float mean = s * (1.0f / 256.0f);
        float var = sq * (1.0f / 256.0f) - mean * mean;
        sMean[le] = mean;
        sInv[le] = rsqrtf(var + 1e-5f);
    }
    __syncthreads();
    int nE = E - basee; if (nE > 32) nE = 32;
    // thread t owns columns {2t, 2t+1} of the 512-wide row
    int c2 = t * 2;
    float2 cs2 = *(const float2*)(colsum + c2);
#pragma unroll 4
    for (int ee = 0; ee < nE; ee++) {
        int ni = sNi[ee], ti = sTi[ee], vi = sVi[ee];
        float inv = sInv[ee];
        float mi = sMean[ee] * inv;
        float2 a = *(const float2*)(nW + (size_t)ni * 512 + c2);
        float2 b = *(const float2*)(tW + (size_t)ti * 512 + c2);
        float2 c = *(const float2*)(vW + (size_t)vi * 512 + c2);
        float2 o;
        o.x = inv * (a.x + b.x + c.x) - mi * cs2.x;
        o.y = inv * (a.y + b.y + c.y) - mi * cs2.y;
        *(float2*)(KV + (size_t)sPos[ee] * 512 + c2) = o;
    }
}

// ---------------- LayerNorm ----------------
__global__ void ln_kernel(const float* __restrict__ X, float* __restrict__ Y,
                          const float* __restrict__ w, const float* __restrict__ b, int rows)
{
    int row = blockIdx.x * 8 + (threadIdx.x >> 5);
    int lane = threadIdx.x & 31;
    if (row >= rows) return;
    const float* x = X + (size_t)row * 256;
    float v[8]; float s = 0.f, sq = 0.f;
#pragma unroll
    for (int i = 0; i < 8; i++) { v[i] = x[lane + 32 * i]; s += v[i]; sq += v[i] * v[i]; }
#pragma unroll
    for (int o = 16; o > 0; o >>= 1) {
        s += __shfl_xor_sync(0xffffffffu, s, o);
        sq += __shfl_xor_sync(0xffffffffu, sq, o);
    }
    float mean = s * (1.0f / 256.0f);
    float var = sq * (1.0f / 256.0f) - mean * mean;
    float inv = rsqrtf(var + 1e-5f);
    float* y = Y + (size_t)row * 256;
#pragma unroll
    for (int i = 0; i < 8; i++) {
        int d = lane + 32 * i;
        float o = (v[i] - mean) * inv;
        if (w) o = o * w[d] + b[d];
        y[d] = o;
    }
}

// ---------------- cross-attn Q ----------------
__global__ void qc_kernel(const float* __restrict__ lnlat, const float* __restrict__ Wq,
                          float* __restrict__ qout)
{
    int l = blockIdx.x;
    int c = threadIdx.x;
    float s = 0.f;
#pragma unroll 8
    for (int k = 0; k < 256; k++) s += lnlat[l * 256 + k] * Wq[k * 256 + c];
    int h = c >> 5, dh = c & 31;
    qout[(h * 64 + l) * 32 + dh] = s * 0.17677669529663689f;
}

// ---------------- dense sorted cross-attn scan ----------------
// grid (NCHUNK, 16); 512 threads = 8 heads x 64 latents; 16-event smem tiles
__global__ __launch_bounds__(512) void attn_scan_sorted(
    const float* __restrict__ KV, const float* __restrict__ qg,
    const int* __restrict__ bo,
    float* __restrict__ pO, float* __restrict__ pZ)
{
    __shared__ float sKV[16 * 512];
    int t = threadIdx.x;
    int h = t >> 6, l = t & 63;
    int b = blockIdx.y, chunk = blockIdx.x;
    int start = bo[b], end = bo[b + 1];
    int cntb = end - start;
    int len = (cntb + NCHUNK - 1) / NCHUNK;
    int s0 = start + chunk * len;
    int s1 = s0 + len; if (s1 > end) s1 = end;

    float q[32];
    {
        const float4* qp = (const float4*)(qg + (h * 64 + l) * 32);
#pragma unroll
        for (int j = 0; j < 8; j++) {
            float4 v = qp[j];
            q[j * 4 + 0] = v.x; q[j * 4 + 1] = v.y; q[j * 4 + 2] = v.z; q[j * 4 + 3] = v.w;
        }
    }
    float accO[32];
#pragma unroll
    for (int j = 0; j < 32; j++) accO[j] = 0.f;
    float z = 0.f;

    const float4* KV4 = (const float4*)KV;
    for (int tile = s0; tile < s1; tile += 16) {
        int nt = s1 - tile; if (nt > 16) nt = 16;
        __syncthreads();
        int nq = nt * 128;  // float4 count
        float4* d4 = (float4*)sKV;
        for (int i = t; i < nq; i += 512) d4[i] = KV4[(size_t)tile * 128 + i];
        __syncthreads();
        for (int e = 0; e < nt; e++) {
            const float4* kp4 = (const float4*)(sKV + e * 512 + h * 32);
            float sc = 0.f;
#pragma unroll
            for (int j = 0; j < 8; j++) {
                float4 k4 = kp4[j];
                sc += q[j * 4 + 0] * k4.x + q[j * 4 + 1] * k4.y
                    + q[j * 4 + 2] * k4.z + q[j * 4 + 3] * k4.w;
            }
            float p = __expf(sc);
            z += p;
            const float4* vp4 = kp4 + 64;  // +256 floats
#pragma unroll
            for (int j = 0; j < 8; j++) {
                float4 v4 = vp4[j];
                accO[j * 4 + 0] += p * v4.x; accO[j * 4 + 1] += p * v4.y;
                accO[j * 4 + 2] += p * v4.z; accO[j * 4 + 3] += p * v4.w;
            }
        }
    }
    size_t pb = (size_t)((b * 8 + h) * NCHUNK + chunk);
    float4* po4 = (float4*)(pO + pb * 2048 + l * 32);
#pragma unroll
    for (int j = 0; j < 8; j++)
        po4[j] = make_float4(accO[j * 4], accO[j * 4 + 1], accO[j * 4 + 2], accO[j * 4 + 3]);
    pZ[pb * 64 + l] = z;
}

// ---------------- combine chunk partials ----------------
__global__ void attn_combine_kernel(const float* __restrict__ pO, const float* __restrict__ pZ,
                                    float* __restrict__ attn)
{
    int bh = blockIdx.x;
    int b = bh >> 3, h = bh & 7;
    int t = threadIdx.x;
    __shared__ float sz[64];
    if (t < 64) {
        float zz = 0.f;
        for (int c = 0; c < NCHUNK; c++) zz += pZ[((size_t)bh * NCHUNK + c) * 64 + t];
        sz[t] = 1.0f / zz;
    }
    __syncthreads();
    for (int i = t; i < 2048; i += 256) {
        int l = i >> 5, d = i & 31;
        float s = 0.f;
        for (int c = 0; c < NCHUNK; c++) s += pO[((size_t)bh * NCHUNK + c) * 2048 + i];
        attn[(size_t)(b * 64 + l) * 256 + h * 32 + d] = s * sz[l];
    }
}

// ---------------- self-attention over latents ----------------
__global__ __launch_bounds__(256) void self_attn_kernel(const float* __restrict__ qkv,
                                                        float* __restrict__ out)
{
    int b = blockIdx.x, h = blockIdx.y;
    __shared__ float sk[2048], sv[2048];
    int t = threadIdx.x;
    for (int i = t; i < 2048; i += 256) {
        int key = i >> 5, d = i & 31;
        size_t rowb = (size_t)(b * 64 + key) * 768;
        sk[i] = qkv[rowb + 256 + h * 32 + d];
        sv[i] = qkv[rowb + 512 + h * 32 + d];
    }
    __syncthreads();
    int ql = t >> 2, r = t & 3;
    const float* qp = qkv + (size_t)(b * 64 + ql) * 768 + h * 32 + r * 8;
    float qv[8];
#pragma unroll
    for (int j = 0; j < 8; j++) qv[j] = qp[j] * 0.17677669529663689f;
    float z = 0.f;
    for (int key = 0; key < 64; key++) {
        float part = 0.f;
#pragma unroll
        for (int j = 0; j < 8; j++) part += qv[j] * sk[key * 32 + r * 8 + j];
        part += __shfl_xor_sync(0xffffffffu, part, 1);
        part += __shfl_xor_sync(0xffffffffu, part, 2);
        z += __expf(part);
    }
    float o[8] = {0.f, 0.f, 0.f, 0.f, 0.f, 0.f, 0.f, 0.f};
    for (int key = 0; key < 64; key++) {
        float part = 0.f;
#pragma unroll
        for (int j = 0; j < 8; j++) part += qv[j] * sk[key * 32 + r * 8 + j];
        part += __shfl_xor_sync(0xffffffffu, part, 1);
        part += __shfl_xor_sync(0xffffffffu, part, 2);
        float p = __expf(part);
#pragma unroll
        for (int j = 0; j < 8; j++) o[j] += p * sv[key * 32 + r * 8 + j];
    }
    float invz = 1.0f / z;
#pragma unroll
    for (int j = 0; j < 8; j++)
        out[(size_t)(b * 64 + ql) * 256 + h * 32 + r * 8 + j] = o[j] * invz;
}

// ---------------- behavior query ----------------
__global__ void qb_kernel(const float* __restrict__ bhq, const float* __restrict__ wq,
                          float* __restrict__ qb)
{
    int t = threadIdx.x;
    int be = t >> 8, c = t & 255;
    float s = 0.f;
#pragma unroll 8
    for (int k = 0; k < 256; k++) s += bhq[be * 256 + k] * wq[k * 256 + c];
    int h = c >> 5, dh = c & 31;
    qb[(h * 2 + be) * 32 + dh] = s * 0.17677669529663689f;
}

// ---------------- behavior attention ----------------
__global__ void bh_attn_kernel(const float* __restrict__ kvb, const float* __restrict__ qb,
                               float* __restrict__ bo)
{
    int b = blockIdx.x, h = blockIdx.y;
    __shared__ float sk[2048], sv[2048];
    int t = threadIdx.x;
    for (int i = t; i < 2048; i += 64) {
        int key = i >> 5, d = i & 31;
        size_t rowb = (size_t)(b * 64 + key) * 512;
        sk[i] = kvb[rowb + h * 32 + d];
        sv[i] = kvb[rowb + 256 + h * 32 + d];
    }
    __syncthreads();
    int be = t >> 5, d = t & 31;
    float q[32];
#pragma unroll
    for (int j = 0; j < 32; j++) q[j] = qb[(h * 2 + be) * 32 + j];
    float z = 0.f, o = 0.f;
    for (int key = 0; key < 64; key++) {
        float s = 0.f;
#pragma unroll
        for (int j = 0; j < 32; j++) s += q[j] * sk[key * 32 + j];
        float p = __expf(s);
        z += p;
        o += p * sv[key * 32 + d];
    }
    bo[(size_t)(b * 2 + be) * 256 + h * 32 + d] = o / z;
}

// ---------------- behavior output ----------------
__global__ void bh_out_kernel(const float* __restrict__ bo, const float* __restrict__ wo,
                              float* __restrict__ outBeh)
{
    int t = threadIdx.x;
    int row = t >> 5, lane = t & 31;
    float s = 0.f;
#pragma unroll
    for (int i = 0; i < 8; i++) s += bo[row * 256 + lane + 32 * i] * wo[lane + 32 * i];
#pragma unroll
    for (int o = 16; o > 0; o >>= 1) s += __shfl_xor_sync(0xffffffffu, s, o);
    if (lane == 0) outBeh[row] = s;
}

// ---------------- mean over latents ----------------
__global__ void mean_kernel(const float* __restrict__ lat, float* __restrict__ mn)
{
    int b = blockIdx.x, d = threadIdx.x;
    float s = 0.f;
#pragma unroll 8
    for (int l = 0; l < 64; l++) s += lat[(size_t)(b * 64 + l) * 256 + d];
    mn[b * 256 + d] = s * (1.0f / 64.0f);
}

// ---------------- logits ----------------
__global__ void logits_kernel(const float* __restrict__ mn, const float* __restrict__ spw,
                              const float* __restrict__ spb, float* __restrict__ out)
{
    int t = threadIdx.x;
    int b = t >> 6, s = t & 63;
    float acc = spb[s];
#pragma unroll 8
    for (int k = 0; k < 256; k++) acc += mn[b * 256 + k] * spw[k * 64 + s];
    out[b * 64 + s] = acc;
}

// ---------------- host launcher ----------------
extern "C" void kernel_launch(void* const* d_in, const int* in_sizes, int n_in,
                              void* d_out, int out_size)
{
    int ib, wb;
    if (in_sizes[0] == in_sizes[1] && in_sizes[1] == in_sizes[2] && in_sizes[2] == in_sizes[3]) {
        ib = 0; wb = n_in - 21;
    } else {
        wb = 0; ib = 21;
    }
    const int* nid  = (const int*)d_in[ib + 0];
    const int* tbi  = (const int*)d_in[ib + 1];
    const int* vli  = (const int*)d_in[ib + 2];
    const int* bidx = (const int*)d_in[ib + 3];
    int E = in_sizes[ib];
    if (E > EVCAP) E = EVCAP;

    const float* nemb    = (const float*)d_in[wb + 0];
    const float* temb    = (const float*)d_in[wb + 1];
    const float* vemb    = (const float*)d_in[wb + 2];
    const float* lat0    = (const float*)d_in[wb + 3];
    const float* Wq_c    = (const float*)d_in[wb + 4];
    const float* Wkv_c   = (const float*)d_in[wb + 5];
    const float* Wo_c    = (const float*)d_in[wb + 6];
    const float* W1_c    = (const float*)d_in[wb + 7];
    const float* W2_c    = (const float*)d_in[wb + 8];
    const float* Wqkv_s  = (const float*)d_in[wb + 9];
    const float* Wo_s    = (const float*)d_in[wb + 10];
    const float* W1_s    = (const float*)d_in[wb + 11];
    const float* W2_s    = (const float*)d_in[wb + 12];
    const float* bh_query = (const float*)d_in[wb + 13];
    const float* bh_wq   = (const float*)d_in[wb + 14];
    const float* bh_wkv  = (const float*)d_in[wb + 15];
    const float* bh_wo   = (const float*)d_in[wb + 16];
    const float* bh_ln_w = (const float*)d_in[wb + 17];
    const float* bh_ln_b = (const float*)d_in[wb + 18];
    const float* sp_w    = (const float*)d_in[wb + 19];
    const float* sp_b    = (const float*)d_in[wb + 20];

    float* buf = nullptr;
    cudaGetSymbolAddress((void**)&buf, g_buf);
    int* ibuf = nullptr;
    cudaGetSymbolAddress((void**)&ibuf, g_ibuf);

    float* KV   = buf + O_KV;
    float* nW   = buf + O_NW;
    float* tW   = buf + O_TW;
    float* vW   = buf + O_VW;
    float* CS   = buf + O_CS;
    float* Qg   = buf + O_Q;
    float* PO   = buf + O_PO;
    float* PZ   = buf + O_PZ;
    float* LAT  = buf + O_LAT;
    float* LNB  = buf + O_LN;
    float* T1   = buf + O_T1;
    float* T2   = buf + O_T2;
    float* AT   = buf + O_AT;
    float* XB   = buf + O_XB;
    float* KB   = buf + O_KB;
    float* QB   = buf + O_QB;
    float* BO   = buf + O_BO2;
    float* MN   = buf + O_MEAN;
    int* CNT  = ibuf + I_CNT;
    int* BASE = ibuf + I_BASE;
    int* BOFF = ibuf + I_BO;
    float* out = (float*)d_out;

    int G256 = (E + 255) / 256;
    int G32  = (E + 31) / 32;

    // [0] histogram, [1] offsets+colsum, [2] fused table GEMMs, [3] event KV (profiled slot)
    hist32_kernel<<<G256, 256>>>(bidx, CNT, E);
    scanoffs_kernel<<<1, 512>>>(CNT, G32, Wkv_c, CS, BASE, BOFF, E);
    gemm_all<<<dim3(8, 64, 3), 256>>>(nemb, temb, vemb, Wkv_c, nW, tW, vW);
    event_kv_kernel<<<G32, 256>>>(nid, tbi, vli, bidx, nemb, temb, vemb,
                                  nW, tW, vW, CS, BASE, BOFF, KV, E);

    // Cross-attention
    ln_kernel<<<8, 256>>>(lat0, LNB, nullptr, nullptr, 64);
    qc_kernel<<<64, 256>>>(LNB, Wq_c, Qg);
    attn_scan_sorted<<<dim3(NCHUNK, 16), 512>>>(KV, Qg, BOFF, PO, PZ);
    attn_combine_kernel<<<128, 256>>>(PO, PZ, AT);

    // lat = lat_init + attn @ Wo_c
    gemm_epi<<<dim3(4, 16), 256>>>(AT, Wo_c, LAT, 1024, 256, 256, lat0, 64, nullptr, 0);
    // lat += gelu(ln(lat) @ W1_c) @ W2_c
    ln_kernel<<<128, 256>>>(LAT, LNB, nullptr, nullptr, 1024);
    gemm_epi<<<dim3(16, 16), 256>>>(LNB, W1_c, T1, 1024, 256, 1024, nullptr, 1, nullptr, 1);
    gemm_epi<<<dim3(4, 16), 256>>>(T1, W2_c, LAT, 1024, 1024, 256, LAT, 1024, nullptr, 0);

    // Self-attention layers
    for (int i = 0; i < 2; i++) {
        ln_kernel<<<128, 256>>>(LAT, LNB, nullptr, nullptr, 1024);
        gemm_epi<<<dim3(12, 16), 256>>>(LNB, Wqkv_s + (size_t)i * 256 * 768, T2, 1024, 256, 768,
                                        nullptr, 1, nullptr, 0);
        self_attn_kernel<<<dim3(16, 8), 256>>>(T2, AT);
        gemm_epi<<<dim3(4, 16), 256>>>(AT, Wo_s + (size_t)i * 256 * 256, LAT, 1024, 256, 256,
                                       LAT, 1024, nullptr, 0);
        ln_kernel<<<128, 256>>>(LAT, LNB, nullptr, nullptr, 1024);
        gemm_epi<<<dim3(16, 16), 256>>>(LNB, W1_s + (size_t)i * 256 * 1024, T1, 1024, 256, 1024,
                                        nullptr, 1, nullptr, 1);
        gemm_epi<<<dim3(4, 16), 256>>>(T1, W2_s + (size_t)i * 1024 * 256, LAT, 1024, 1024, 256,
                                       LAT, 1024, nullptr, 0);
    }

    // Behavior decoder
    ln_kernel<<<128, 256>>>(LAT, XB, bh_ln_w, bh_ln_b, 1024);
    qb_kernel<<<1, 512>>>(bh_query, bh_wq, QB);
    gemm_epi<<<dim3(8, 16), 256>>>(XB, bh_wkv, KB, 1024, 256, 512, nullptr, 1, nullptr, 0);
    bh_attn_kernel<<<dim3(16, 8), 64>>>(KB, QB, BO);
    bh_out_kernel<<<1, 1024>>>(BO, bh_wo, out);

    // Spike head
    mean_kernel<<<16, 256>>>(LAT, MN);
    logits_kernel<<<1, 1024>>>(MN, sp_w, sp_b, out + 32);
}

// round 13
// speedup vs baseline: 1.6460x; 1.0338x over previous
#include <cuda_runtime.h>
#include <cuda_bf16.h>
#include <math.h>
#include <stdint.h>

// ---------------- constants ----------------
#define NCHUNK 32
#define EVCAP  204800

// ---------------- float scratch ----------------
static constexpr size_t O_KV = 0;                                   // (EVCAP,512) bf16 sorted k|v (uses half the region)
static constexpr size_t O_NW = O_KV + (size_t)EVCAP * 512;          // 4096x512
static constexpr size_t O_TW = O_NW + (size_t)4096 * 512;           // 1024x512
static constexpr size_t O_VW = O_TW + (size_t)1024 * 512;           // 256x512
static constexpr size_t O_CS = O_VW + (size_t)256 * 512;            // 512 colsum
static constexpr size_t O_Q  = O_CS + 512;                          // (H,64,32)
static constexpr size_t O_PO = O_Q + 8 * 64 * 32;                   // (B,H,NCHUNK,64,32)
static constexpr size_t O_PZ = O_PO + (size_t)16 * 8 * NCHUNK * 64 * 32;
static constexpr size_t O_LAT = O_PZ + (size_t)16 * 8 * NCHUNK * 64;
static constexpr size_t O_LN  = O_LAT + 1024 * 256;
static constexpr size_t O_T1  = O_LN + 1024 * 256;
static constexpr size_t O_T2  = O_T1 + 1024 * 1024;
static constexpr size_t O_AT  = O_T2 + 1024 * 768;
static constexpr size_t O_XB  = O_AT + 1024 * 256;
static constexpr size_t O_KB  = O_XB + 1024 * 256;
static constexpr size_t O_QB  = O_KB + 1024 * 512;
static constexpr size_t O_BO2 = O_QB + 512;
static constexpr size_t O_MEAN = O_BO2 + 16 * 2 * 256;
static constexpr size_t SCRATCH_TOTAL = O_MEAN + 16 * 256;

__device__ float g_buf[SCRATCH_TOTAL];

// ---------------- int scratch (sorting) ----------------
static constexpr size_t I_CNT  = 0;
static constexpr size_t I_BASE = 102400;
static constexpr size_t I_BO   = 204800;
__device__ int g_ibuf[204832];

__device__ __forceinline__ float gelu_f(float x) {
    float x3 = x * x * x;
    return 0.5f * x * (1.0f + tanhf(0.7978845608028654f * (x + 0.044715f * x3)));
}

// ---------------- packed f32x2 helpers (Blackwell FFMA2) ----------------
__device__ __forceinline__ unsigned long long pk2(float a, float b) {
    unsigned long long r;
    asm("mov.b64 %0,{%1,%2};" : "=l"(r) : "f"(a), "f"(b));
    return r;
}
__device__ __forceinline__ float2 upk2(unsigned long long v) {
    float2 f;
    asm("mov.b64 {%0,%1},%2;" : "=f"(f.x), "=f"(f.y) : "l"(v));
    return f;
}
__device__ __forceinline__ unsigned long long fma2(unsigned long long a,
                                                   unsigned long long b,
                                                   unsigned long long c) {
    unsigned long long r;
    asm("fma.rn.f32x2 %0,%1,%2,%3;" : "=l"(r) : "l"(a), "l"(b), "l"(c));
    return r;
}

// ---------------- tiled GEMM 64x64 + epilogue ----------------
__global__ __launch_bounds__(256) void gemm_epi(
    const float* __restrict__ A, const float* __restrict__ W, float* __restrict__ C,
    int M, int K, int N, const float* __restrict__ res, int resMod,
    const float* __restrict__ bias, int doGelu)
{
    __shared__ float As[16][68];
    __shared__ float Bs[16][64];
    int t = threadIdx.x;
    int tx = t & 15, ty = t >> 4;
    int row0 = blockIdx.y * 64, col0 = blockIdx.x * 64;
    float acc[4][4] = {};
    int ar = t >> 2, ac = (t & 3) * 4;
    int br = t >> 4, bc = (t & 15) * 4;
    for (int k0 = 0; k0 < K; k0 += 16) {
        float4 a4 = *(const float4*)(A + (size_t)(row0 + ar) * K + k0 + ac);
        As[ac + 0][ar] = a4.x; As[ac + 1][ar] = a4.y;
        As[ac + 2][ar] = a4.z; As[ac + 3][ar] = a4.w;
        *(float4*)&Bs[br][bc] = *(const float4*)(W + (size_t)(k0 + br) * N + col0 + bc);
        __syncthreads();
#pragma unroll
        for (int kk = 0; kk < 16; kk++) {
            float4 av = *(const float4*)&As[kk][ty * 4];
            float4 bv = *(const float4*)&Bs[kk][tx * 4];
            acc[0][0] += av.x * bv.x; acc[0][1] += av.x * bv.y; acc[0][2] += av.x * bv.z; acc[0][3] += av.x * bv.w;
            acc[1][0] += av.y * bv.x; acc[1][1] += av.y * bv.y; acc[1][2] += av.y * bv.z; acc[1][3] += av.y * bv.w;
            acc[2][0] += av.z * bv.x; acc[2][1] += av.z * bv.y; acc[2][2] += av.z * bv.z; acc[2][3] += av.z * bv.w;
            acc[3][0] += av.w * bv.x; acc[3][1] += av.w * bv.y; acc[3][2] += av.w * bv.z; acc[3][3] += av.w * bv.w;
        }
        __syncthreads();
    }
#pragma unroll
    for (int i = 0; i < 4; i++) {
        int r = row0 + ty * 4 + i;
#pragma unroll
        for (int j = 0; j < 4; j++) {
            int c = col0 + tx * 4 + j;
            float v = acc[i][j];
            if (bias) v += bias[c];
            if (doGelu) v = gelu_f(v);
            if (res) v += res[(size_t)(r % resMod) * N + c];
            C[(size_t)r * N + c] = v;
        }
    }
}

// ---------------- fused: all three table projections, 64x64 tiles ----------------
__global__ __launch_bounds__(256) void gemm_all(
    const float* __restrict__ A0, const float* __restrict__ A1, const float* __restrict__ A2,
    const float* __restrict__ W,
    float* __restrict__ C0, float* __restrict__ C1, float* __restrict__ C2)
{
    int z = blockIdx.z;
    const float* A; float* C; int ymax;
    if (z == 0) { A = A0; C = C0; ymax = 64; }
    else if (z == 1) { A = A1; C = C1; ymax = 16; }
    else { A = A2; C = C2; ymax = 4; }
    if (blockIdx.y >= ymax) return;
    const int K = 256, N = 512;
    __shared__ float As[16][68];
    __shared__ float Bs[16][64];
    int t = threadIdx.x;
    int tx = t & 15, ty = t >> 4;
    int row0 = blockIdx.y * 64, col0 = blockIdx.x * 64;
    float acc[4][4] = {};
    int ar = t >> 2, ac = (t & 3) * 4;
    int br = t >> 4, bc = (t & 15) * 4;
    for (int k0 = 0; k0 < K; k0 += 16) {
        float4 a4 = *(const float4*)(A + (size_t)(row0 + ar) * K + k0 + ac);
        As[ac + 0][ar] = a4.x; As[ac + 1][ar] = a4.y;
        As[ac + 2][ar] = a4.z; As[ac + 3][ar] = a4.w;
        *(float4*)&Bs[br][bc] = *(const float4*)(W + (size_t)(k0 + br) * N + col0 + bc);
        __syncthreads();
#pragma unroll
        for (int kk = 0; kk < 16; kk++) {
            float4 av = *(const float4*)&As[kk][ty * 4];
            float4 bv = *(const float4*)&Bs[kk][tx * 4];
            acc[0][0] += av.x * bv.x; acc[0][1] += av.x * bv.y; acc[0][2] += av.x * bv.z; acc[0][3] += av.x * bv.w;
            acc[1][0] += av.y * bv.x; acc[1][1] += av.y * bv.y; acc[1][2] += av.y * bv.z; acc[1][3] += av.y * bv.w;
            acc[2][0] += av.z * bv.x; acc[2][1] += av.z * bv.y; acc[2][2] += av.z * bv.z; acc[2][3] += av.z * bv.w;
            acc[3][0] += av.w * bv.x; acc[3][1] += av.w * bv.y; acc[3][2] += av.w * bv.z; acc[3][3] += av.w * bv.w;
        }
        __syncthreads();
    }
#pragma unroll
    for (int i = 0; i < 4; i++) {
        int r = row0 + ty * 4 + i;
#pragma unroll
        for (int j = 0; j < 4; j++)
            C[(size_t)r * 512 + col0 + tx * 4 + j] = acc[i][j];
    }
}

// ---------------- sort step 1 ----------------
__global__ void hist32_kernel(const int* __restrict__ bidx, int* __restrict__ cnt, int E)
{
    int t = threadIdx.x;
    int e = blockIdx.x * 256 + t;
    int w = t >> 5, lane = t & 31;
    int b = (e < E) ? bidx[e] : -1;
    int g = blockIdx.x * 8 + w;
#pragma unroll
    for (int bb = 0; bb < 16; bb++) {
        unsigned m = __ballot_sync(0xffffffffu, b == bb);
        if (lane == 0) cnt[g * 16 + bb] = __popc(m);
    }
}

// ---------------- sort step 2 + colsum ----------------
__global__ void scanoffs_kernel(const int* __restrict__ cnt, int G32,
                                const float* __restrict__ Wkv, float* __restrict__ CS,
                                int* __restrict__ base, int* __restrict__ bo, int E)
{
    int t = threadIdx.x;
    {
        float s = 0.f;
#pragma unroll 8
        for (int k = 0; k < 256; k++) s += Wkv[k * 512 + t];
        CS[t] = s;
    }
    __shared__ int tot[16];
    int b = t >> 5, lane = t & 31;
    int seg = (G32 + 31) / 32;
    int g0 = lane * seg, g1 = g0 + seg; if (g1 > G32) g1 = G32; if (g0 > G32) g0 = G32;
    int s = 0;
    for (int g = g0; g < g1; g++) s += cnt[g * 16 + b];
    int incl = s;
#pragma unroll
    for (int o = 1; o < 32; o <<= 1) {
        int v = __shfl_up_sync(0xffffffffu, incl, o);
        if (lane >= o) incl += v;
    }
    int run = incl - s;
    for (int g = g0; g < g1; g++) {
        int c = cnt[g * 16 + b];
        base[g * 16 + b] = run;
        run += c;
    }
    if (lane == 31) tot[b] = incl;
    __syncthreads();
    if (t == 0) {
        int acc = 0;
        for (int bb = 0; bb < 16; bb++) { bo[bb] = acc; acc += tot[bb]; }
        bo[16] = acc;
    }
}

// ---------------- per-event KV (batch-sorted, bf16 output) ----------------
__global__ __launch_bounds__(256) void event_kv_kernel(
    const int* __restrict__ nid, const int* __restrict__ tbi, const int* __restrict__ vli,
    const int* __restrict__ bidx,
    const float* __restrict__ nemb, const float* __restrict__ temb, const float* __restrict__ vemb,
    const float* __restrict__ nW, const float* __restrict__ tW, const float* __restrict__ vW,
    const float* __restrict__ colsum,
    const int* __restrict__ base32, const int* __restrict__ bo,
    __nv_bfloat162* __restrict__ KVh, int E)
{
    __shared__ float sMean[32], sInv[32];
    __shared__ int sNi[32], sTi[32], sVi[32], sPos[32];
    int t = threadIdx.x;
    int g = blockIdx.x;
    int basee = g * 32;
    if (t < 32) {
        int e = basee + t;
        int b = (e < E) ? bidx[e] : -1;
        int rank = 0;
#pragma unroll
        for (int bb = 0; bb < 16; bb++) {
            unsigned m = __ballot_sync(0xffffffffu, b == bb);
            if (b == bb) rank = __popc(m & ((1u << t) - 1u));
        }
        if (e < E) sPos[t] = bo[b] + base32[g * 16 + b] + rank;
    }
    int le = t >> 3, g8 = t & 7;
    int e = basee + le;
    float s = 0.f, sq = 0.f;
    if (e < E) {
        int ni = nid[e], ti = tbi[e], vi = vli[e];
        if (g8 == 0) { sNi[le] = ni; sTi[le] = ti; sVi[le] = vi; }
        const float* np = nemb + (size_t)ni * 256;
        const float* tp = temb + (size_t)ti * 256;
        const float* vp = vemb + (size_t)vi * 256;
#pragma unroll
        for (int i = 0; i < 8; i++) {
            int d = g8 * 32 + i * 4;
            float4 a = *(const float4*)(np + d);
            float4 bq = *(const float4*)(tp + d);
            float4 c = *(const float4*)(vp + d);
            float x0 = a.x + bq.x + c.x, x1 = a.y + bq.y + c.y;
            float x2 = a.z + bq.z + c.z, x3 = a.w + bq.w + c.w;
            s += x0 + x1 + x2 + x3;
            sq += x0 * x0 + x1 * x1 + x2 * x2 + x3 * x3;
        }
    }
    s += __shfl_xor_sync(0xffffffffu, s, 1);
    s += __shfl_xor_sync(0xffffffffu, s, 2);
    s += __shfl_xor_sync(0xffffffffu, s, 4);
    sq += __shfl_xor_sync(0xffffffffu, sq, 1);
    sq += __shfl_xor_sync(0xffffffffu, sq, 2);
    sq += __shfl_xor_sync(0xffffffffu, sq, 4);
    if (g8 == 0 && e < E) {
        float mean = s * (1.0f / 256.0f);
        float var = sq * (1.0f / 256.0f) - mean * mean;
        sMean[le] = mean;
        sInv[le] = rsqrtf(var + 1e-5f);
    }
    __syncthreads();
    int nE = E - basee; if (nE > 32) nE = 32;
    int c2 = t * 2;
    float2 cs2 = *(const float2*)(colsum + c2);
#pragma unroll 4
    for (int ee = 0; ee < nE; ee++) {
        int ni = sNi[ee], ti = sTi[ee], vi = sVi[ee];
        float inv = sInv[ee];
        float mi = sMean[ee] * inv;
        float2 a = *(const float2*)(nW + (size_t)ni * 512 + c2);
        float2 b = *(const float2*)(tW + (size_t)ti * 512 + c2);
        float2 c = *(const float2*)(vW + (size_t)vi * 512 + c2);
        float2 o;
        o.x = inv * (a.x + b.x + c.x) - mi * cs2.x;
        o.y = inv * (a.y + b.y + c.y) - mi * cs2.y;
        KVh[(size_t)sPos[ee] * 256 + t] = __float22bfloat162_rn(o);
    }
}

// ---------------- LayerNorm ----------------
__global__ void ln_kernel(const float* __restrict__ X, float* __restrict__ Y,
                          const float* __restrict__ w, const float* __restrict__ b, int rows)
{
    int row = blockIdx.x * 8 + (threadIdx.x >> 5);
    int lane = threadIdx.x & 31;
    if (row >= rows) return;
    const float* x = X + (size_t)row * 256;
    float v[8]; float s = 0.f, sq = 0.f;
#pragma unroll
    for (int i = 0; i < 8; i++) { v[i] = x[lane + 32 * i]; s += v[i]; sq += v[i] * v[i]; }
#pragma unroll
    for (int o = 16; o > 0; o >>= 1) {
        s += __shfl_xor_sync(0xffffffffu, s, o);
        sq += __shfl_xor_sync(0xffffffffu, sq, o);
    }
    float mean = s * (1.0f / 256.0f);
    float var = sq * (1.0f / 256.0f) - mean * mean;
    float inv = rsqrtf(var + 1e-5f);
    float* y = Y + (size_t)row * 256;
#pragma unroll
    for (int i = 0; i < 8; i++) {
        int d = lane + 32 * i;
        float o = (v[i] - mean) * inv;
        if (w) o = o * w[d] + b[d];
        y[d] = o;
    }
}

// ---------------- cross-attn Q ----------------
__global__ void qc_kernel(const float* __restrict__ lnlat, const float* __restrict__ Wq,
                          float* __restrict__ qout)
{
    int l = blockIdx.x;
    int c = threadIdx.x;
    float s = 0.f;
#pragma unroll 8
    for (int k = 0; k < 256; k++) s += lnlat[l * 256 + k] * Wq[k * 256 + c];
    int h = c >> 5, dh = c & 31;
    qout[(h * 64 + l) * 32 + dh] = s * 0.17677669529663689f;
}

// ---------------- dense sorted cross-attn scan (bf16 KV, FFMA2 inner loop) ----------------
// grid (NCHUNK, 16); 512 threads = 8 heads x 64 latents; 16-event fp32 smem tiles
__global__ __launch_bounds__(512) void attn_scan_sorted(
    const __nv_bfloat16* __restrict__ KVh, const float* __restrict__ qg,
    const int* __restrict__ bo,
    float* __restrict__ pO, float* __restrict__ pZ)
{
    __shared__ float sKV[16 * 512];
    int t = threadIdx.x;
    int h = t >> 6, l = t & 63;
    int b = blockIdx.y, chunk = blockIdx.x;
    int start = bo[b], end = bo[b + 1];
    int cntb = end - start;
    int len = (cntb + NCHUNK - 1) / NCHUNK;
    int s0 = start + chunk * len;
    int s1 = s0 + len; if (s1 > end) s1 = end;

    unsigned long long q2[16];
    {
        const float4* qp = (const float4*)(qg + (h * 64 + l) * 32);
#pragma unroll
        for (int j = 0; j < 8; j++) {
            float4 v = qp[j];
            q2[j * 2 + 0] = pk2(v.x, v.y);
            q2[j * 2 + 1] = pk2(v.z, v.w);
        }
    }
    unsigned long long acc2[16];
    const unsigned long long z64 = pk2(0.f, 0.f);
#pragma unroll
    for (int j = 0; j < 16; j++) acc2[j] = z64;
    float z = 0.f;

    for (int tile = s0; tile < s1; tile += 16) {
        int nt = s1 - tile; if (nt > 16) nt = 16;
        __syncthreads();
        // stage bf16 -> fp32 smem: nt*512 bf16 = nt*128 uint2 chunks (4 bf16 each)
        {
            const uint2* src = (const uint2*)(KVh + (size_t)tile * 512);
            float4* dst = (float4*)sKV;
            int nq = nt * 128;
            for (int i = t; i < nq; i += 512) {
                uint2 w = src[i];
                float2 f0 = __bfloat1622float2(*(const __nv_bfloat162*)&w.x);
                float2 f1 = __bfloat1622float2(*(const __nv_bfloat162*)&w.y);
                dst[i] = make_float4(f0.x, f0.y, f1.x, f1.y);
            }
        }
        __syncthreads();
        for (int e = 0; e < nt; e++) {
            const ulonglong2* kp = (const ulonglong2*)(sKV + e * 512 + h * 32);
            unsigned long long sc2 = z64;
#pragma unroll
            for (int j = 0; j < 8; j++) {
                ulonglong2 kk = kp[j];
                sc2 = fma2(q2[j * 2 + 0], kk.x, sc2);
                sc2 = fma2(q2[j * 2 + 1], kk.y, sc2);
            }
            float2 sf = upk2(sc2);
            float p = __expf(sf.x + sf.y);
            z += p;
            unsigned long long p2 = pk2(p, p);
            const ulonglong2* vp = kp + 64;  // +256 floats = +128 ull = +64 ulonglong2
#pragma unroll
            for (int j = 0; j < 8; j++) {
                ulonglong2 vv = vp[j];
                acc2[j * 2 + 0] = fma2(p2, vv.x, acc2[j * 2 + 0]);
                acc2[j * 2 + 1] = fma2(p2, vv.y, acc2[j * 2 + 1]);
            }
        }
    }
    size_t pb = (size_t)((b * 8 + h) * NCHUNK + chunk);
    float4* po4 = (float4*)(pO + pb * 2048 + l * 32);
#pragma unroll
    for (int j = 0; j < 8; j++) {
        float2 a = upk2(acc2[j * 2 + 0]);
        float2 bq = upk2(acc2[j * 2 + 1]);
        po4[j] = make_float4(a.x, a.y, bq.x, bq.y);
    }
    pZ[pb * 64 + l] = z;
}

// ---------------- combine chunk partials ----------------
__global__ void attn_combine_kernel(const float* __restrict__ pO, const float* __restrict__ pZ,
                                    float* __restrict__ attn)
{
    int bh = blockIdx.x;
    int b = bh >> 3, h = bh & 7;
    int t = threadIdx.x;
    __shared__ float sz[64];
    if (t < 64) {
        float zz = 0.f;
        for (int c = 0; c < NCHUNK; c++) zz += pZ[((size_t)bh * NCHUNK + c) * 64 + t];
        sz[t] = 1.0f / zz;
    }
    __syncthreads();
    for (int i = t; i < 2048; i += 256) {
        int l = i >> 5, d = i & 31;
        float s = 0.f;
        for (int c = 0; c < NCHUNK; c++) s += pO[((size_t)bh * NCHUNK + c) * 2048 + i];
        attn[(size_t)(b * 64 + l) * 256 + h * 32 + d] = s * sz[l];
    }
}

// ---------------- self-attention over latents ----------------
__global__ __launch_bounds__(256) void self_attn_kernel(const float* __restrict__ qkv,
                                                        float* __restrict__ out)
{
    int b = blockIdx.x, h = blockIdx.y;
    __shared__ float sk[2048], sv[2048];
    int t = threadIdx.x;
    for (int i = t; i < 2048; i += 256) {
        int key = i >> 5, d = i & 31;
        size_t rowb = (size_t)(b * 64 + key) * 768;
        sk[i] = qkv[rowb + 256 + h * 32 + d];
        sv[i] = qkv[rowb + 512 + h * 32 + d];
    }
    __syncthreads();
    int ql = t >> 2, r = t & 3;
    const float* qp = qkv + (size_t)(b * 64 + ql) * 768 + h * 32 + r * 8;
    float qv[8];
#pragma unroll
    for (int j = 0; j < 8; j++) qv[j] = qp[j] * 0.17677669529663689f;
    float z = 0.f;
    for (int key = 0; key < 64; key++) {
        float part = 0.f;
#pragma unroll
        for (int j = 0; j < 8; j++) part += qv[j] * sk[key * 32 + r * 8 + j];
        part += __shfl_xor_sync(0xffffffffu, part, 1);
        part += __shfl_xor_sync(0xffffffffu, part, 2);
        z += __expf(part);
    }
    float o[8] = {0.f, 0.f, 0.f, 0.f, 0.f, 0.f, 0.f, 0.f};
    for (int key = 0; key < 64; key++) {
        float part = 0.f;
#pragma unroll
        for (int j = 0; j < 8; j++) part += qv[j] * sk[key * 32 + r * 8 + j];
        part += __shfl_xor_sync(0xffffffffu, part, 1);
        part += __shfl_xor_sync(0xffffffffu, part, 2);
        float p = __expf(part);
#pragma unroll
        for (int j = 0; j < 8; j++) o[j] += p * sv[key * 32 + r * 8 + j];
    }
    float invz = 1.0f / z;
#pragma unroll
    for (int j = 0; j < 8; j++)
        out[(size_t)(b * 64 + ql) * 256 + h * 32 + r * 8 + j] = o[j] * invz;
}

// ---------------- behavior query ----------------
__global__ void qb_kernel(const float* __restrict__ bhq, const float* __restrict__ wq,
                          float* __restrict__ qb)
{
    int t = threadIdx.x;
    int be = t >> 8, c = t & 255;
    float s = 0.f;
#pragma unroll 8
    for (int k = 0; k < 256; k++) s += bhq[be * 256 + k] * wq[k * 256 + c];
    int h = c >> 5, dh = c & 31;
    qb[(h * 2 + be) * 32 + dh] = s * 0.17677669529663689f;
}

// ---------------- behavior attention ----------------
__global__ void bh_attn_kernel(const float* __restrict__ kvb, const float* __restrict__ qb,
                               float* __restrict__ bo)
{
    int b = blockIdx.x, h = blockIdx.y;
    __shared__ float sk[2048], sv[2048];
    int t = threadIdx.x;
    for (int i = t; i < 2048; i += 64) {
        int key = i >> 5, d = i & 31;
        size_t rowb = (size_t)(b * 64 + key) * 512;
        sk[i] = kvb[rowb + h * 32 + d];
        sv[i] = kvb[rowb + 256 + h * 32 + d];
    }
    __syncthreads();
    int be = t >> 5, d = t & 31;
    float q[32];
#pragma unroll
    for (int j = 0; j < 32; j++) q[j] = qb[(h * 2 + be) * 32 + j];
    float z = 0.f, o = 0.f;
    for (int key = 0; key < 64; key++) {
        float s = 0.f;
#pragma unroll
        for (int j = 0; j < 32; j++) s += q[j] * sk[key * 32 + j];
        float p = __expf(s);
        z += p;
        o += p * sv[key * 32 + d];
    }
    bo[(size_t)(b * 2 + be) * 256 + h * 32 + d] = o / z;
}

// ---------------- behavior output ----------------
__global__ void bh_out_kernel(const float* __restrict__ bo, const float* __restrict__ wo,
                              float* __restrict__ outBeh)
{
    int t = threadIdx.x;
    int row = t >> 5, lane = t & 31;
    float s = 0.f;
#pragma unroll
    for (int i = 0; i < 8; i++) s += bo[row * 256 + lane + 32 * i] * wo[lane + 32 * i];
#pragma unroll
    for (int o = 16; o > 0; o >>= 1) s += __shfl_xor_sync(0xffffffffu, s, o);
    if (lane == 0) outBeh[row] = s;
}

// ---------------- mean over latents ----------------
__global__ void mean_kernel(const float* __restrict__ lat, float* __restrict__ mn)
{
    int b = blockIdx.x, d = threadIdx.x;
    float s = 0.f;
#pragma unroll 8
    for (int l = 0; l < 64; l++) s += lat[(size_t)(b * 64 + l) * 256 + d];
    mn[b * 256 + d] = s * (1.0f / 64.0f);
}

// ---------------- logits ----------------
__global__ void logits_kernel(const float* __restrict__ mn, const float* __restrict__ spw,
                              const float* __restrict__ spb, float* __restrict__ out)
{
    int t = threadIdx.x;
    int b = t >> 6, s = t & 63;
    float acc = spb[s];
#pragma unroll 8
    for (int k = 0; k < 256; k++) acc += mn[b * 256 + k] * spw[k * 64 + s];
    out[b * 64 + s] = acc;
}

// ---------------- host launcher ----------------
extern "C" void kernel_launch(void* const* d_in, const int* in_sizes, int n_in,
                              void* d_out, int out_size)
{
    int ib, wb;
    if (in_sizes[0] == in_sizes[1] && in_sizes[1] == in_sizes[2] && in_sizes[2] == in_sizes[3]) {
        ib = 0; wb = n_in - 21;
    } else {
        wb = 0; ib = 21;
    }
    const int* nid  = (const int*)d_in[ib + 0];
    const int* tbi  = (const int*)d_in[ib + 1];
    const int* vli  = (const int*)d_in[ib + 2];
    const int* bidx = (const int*)d_in[ib + 3];
    int E = in_sizes[ib];
    if (E > EVCAP) E = EVCAP;

    const float* nemb    = (const float*)d_in[wb + 0];
    const float* temb    = (const float*)d_in[wb + 1];
    const float* vemb    = (const float*)d_in[wb + 2];
    const float* lat0    = (const float*)d_in[wb + 3];
    const float* Wq_c    = (const float*)d_in[wb + 4];
    const float* Wkv_c   = (const float*)d_in[wb + 5];
    const float* Wo_c    = (const float*)d_in[wb + 6];
    const float* W1_c    = (const float*)d_in[wb + 7];
    const float* W2_c    = (const float*)d_in[wb + 8];
    const float* Wqkv_s  = (const float*)d_in[wb + 9];
    const float* Wo_s    = (const float*)d_in[wb + 10];
    const float* W1_s    = (const float*)d_in[wb + 11];
    const float* W2_s    = (const float*)d_in[wb + 12];
    const float* bh_query = (const float*)d_in[wb + 13];
    const float* bh_wq   = (const float*)d_in[wb + 14];
    const float* bh_wkv  = (const float*)d_in[wb + 15];
    const float* bh_wo   = (const float*)d_in[wb + 16];
    const float* bh_ln_w = (const float*)d_in[wb + 17];
    const float* bh_ln_b = (const float*)d_in[wb + 18];
    const float* sp_w    = (const float*)d_in[wb + 19];
    const float* sp_b    = (const float*)d_in[wb + 20];

    float* buf = nullptr;
    cudaGetSymbolAddress((void**)&buf, g_buf);
    int* ibuf = nullptr;
    cudaGetSymbolAddress((void**)&ibuf, g_ibuf);

    __nv_bfloat16* KVh = (__nv_bfloat16*)(buf + O_KV);
    float* nW   = buf + O_NW;
    float* tW   = buf + O_TW;
    float* vW   = buf + O_VW;
    float* CS   = buf + O_CS;
    float* Qg   = buf + O_Q;
    float* PO   = buf + O_PO;
    float* PZ   = buf + O_PZ;
    float* LAT  = buf + O_LAT;
    float* LNB  = buf + O_LN;
    float* T1   = buf + O_T1;
    float* T2   = buf + O_T2;
    float* AT   = buf + O_AT;
    float* XB   = buf + O_XB;
    float* KB   = buf + O_KB;
    float* QB   = buf + O_QB;
    float* BO   = buf + O_BO2;
    float* MN   = buf + O_MEAN;
    int* CNT  = ibuf + I_CNT;
    int* BASE = ibuf + I_BASE;
    int* BOFF = ibuf + I_BO;
    float* out = (float*)d_out;

    int G256 = (E + 255) / 256;
    int G32  = (E + 31) / 32;

    // [0] histogram, [1] offsets+colsum, [2] fused table GEMMs, [3] event KV (profiled slot)
    hist32_kernel<<<G256, 256>>>(bidx, CNT, E);
    scanoffs_kernel<<<1, 512>>>(CNT, G32, Wkv_c, CS, BASE, BOFF, E);
    gemm_all<<<dim3(8, 64, 3), 256>>>(nemb, temb, vemb, Wkv_c, nW, tW, vW);
    event_kv_kernel<<<G32, 256>>>(nid, tbi, vli, bidx, nemb, temb, vemb,
                                  nW, tW, vW, CS, BASE, BOFF,
                                  (__nv_bfloat162*)KVh, E);

    // Cross-attention
    ln_kernel<<<8, 256>>>(lat0, LNB, nullptr, nullptr, 64);
    qc_kernel<<<64, 256>>>(LNB, Wq_c, Qg);
    attn_scan_sorted<<<dim3(NCHUNK, 16), 512>>>(KVh, Qg, BOFF, PO, PZ);
    attn_combine_kernel<<<128, 256>>>(PO, PZ, AT);

    // lat = lat_init + attn @ Wo_c
    gemm_epi<<<dim3(4, 16), 256>>>(AT, Wo_c, LAT, 1024, 256, 256, lat0, 64, nullptr, 0);
    // lat += gelu(ln(lat) @ W1_c) @ W2_c
    ln_kernel<<<128, 256>>>(LAT, LNB, nullptr, nullptr, 1024);
    gemm_epi<<<dim3(16, 16), 256>>>(LNB, W1_c, T1, 1024, 256, 1024, nullptr, 1, nullptr, 1);
    gemm_epi<<<dim3(4, 16), 256>>>(T1, W2_c, LAT, 1024, 1024, 256, LAT, 1024, nullptr, 0);

    // Self-attention layers
    for (int i = 0; i < 2; i++) {
        ln_kernel<<<128, 256>>>(LAT, LNB, nullptr, nullptr, 1024);
        gemm_epi<<<dim3(12, 16), 256>>>(LNB, Wqkv_s + (size_t)i * 256 * 768, T2, 1024, 256, 768,
                                        nullptr, 1, nullptr, 0);
        self_attn_kernel<<<dim3(16, 8), 256>>>(T2, AT);
        gemm_epi<<<dim3(4, 16), 256>>>(AT, Wo_s + (size_t)i * 256 * 256, LAT, 1024, 256, 256,
                                       LAT, 1024, nullptr, 0);
        ln_kernel<<<128, 256>>>(LAT, LNB, nullptr, nullptr, 1024);
        gemm_epi<<<dim3(16, 16), 256>>>(LNB, W1_s + (size_t)i * 256 * 1024, T1, 1024, 256, 1024,
                                        nullptr, 1, nullptr, 1);
        gemm_epi<<<dim3(4, 16), 256>>>(T1, W2_s + (size_t)i * 1024 * 256, LAT, 1024, 1024, 256,
                                       LAT, 1024, nullptr, 0);
    }

    // Behavior decoder
    ln_kernel<<<128, 256>>>(LAT, XB, bh_ln_w, bh_ln_b, 1024);
    qb_kernel<<<1, 512>>>(bh_query, bh_wq, QB);
    gemm_epi<<<dim3(8, 16), 256>>>(XB, bh_wkv, KB, 1024, 256, 512, nullptr, 1, nullptr, 0);
    bh_attn_kernel<<<dim3(16, 8), 64>>>(KB, QB, BO);
    bh_out_kernel<<<1, 1024>>>(BO, bh_wo, out);

    // Spike head
    mean_kernel<<<16, 256>>>(LAT, MN);
    logits_kernel<<<1, 1024>>>(MN, sp_w, sp_b, out + 32);
}